// round 1
// baseline (speedup 1.0000x reference)
#include <cuda_runtime.h>
#include <math.h>

#define NN 100000
#define EE 1600000

// ---------------- static scratch (no runtime allocation allowed) ----------------
__device__ float g_h1[NN * 128];     // x @ W1
__device__ float g_res[NN * 128];    // x @ res_W
__device__ float g_agg1[NN * 128];   // layer1 edge aggregation
__device__ float g_p1[EE * 8];       // per-edge exp(leakyrelu) per head
__device__ float g_asrc1[NN * 8];
__device__ float g_adst1[NN * 8];
__device__ float g_s1[NN * 8];       // softmax denominators (init = p_self)
__device__ float g_h2[NN * 64];      // h @ W2
__device__ float g_agg2[NN * 64];
__device__ float g_p2[EE];
__device__ float g_asrc2[NN];
__device__ float g_adst2[NN];
__device__ float g_s2[NN];

// ---------------- helpers ----------------
__device__ __forceinline__ void red4(float* p, float4 v) {
    asm volatile("red.global.add.v4.f32 [%0], {%1,%2,%3,%4};"
                 :: "l"(p), "f"(v.x), "f"(v.y), "f"(v.z), "f"(v.w) : "memory");
}

__device__ __forceinline__ float lrelu_exp(float v) {
    float e = v > 0.0f ? v : 0.2f * v;
    return __expf(e);
}

__device__ __forceinline__ float warp_sum(float v) {
    #pragma unroll
    for (int o = 16; o > 0; o >>= 1) v += __shfl_xor_sync(0xffffffffu, v, o);
    return v;
}

// ---------------- GEMM: C[M,Ncols] = A[M,128] @ B[128,Ncols] (fp32) ----------------
__global__ void __launch_bounds__(256) gemm_k128(const float* __restrict__ A,
                                                 const float* __restrict__ B,
                                                 float* __restrict__ C,
                                                 int M, int Ncols) {
    __shared__ float As[32][68];   // [k][m], padded
    __shared__ float Bs[32][64];   // [k][n]
    const int tid = threadIdx.x;
    const int m0 = blockIdx.x * 64;
    const int n0 = blockIdx.y * 64;
    const int tm = tid >> 4, tn = tid & 15;
    const int ra = tid >> 3, kq = tid & 7;
    const int kb = tid >> 4, c4 = tid & 15;

    float acc[4][4] = {};

    for (int kc = 0; kc < 128; kc += 32) {
        #pragma unroll
        for (int it = 0; it < 2; it++) {
            int rr = ra + it * 32;
            int m = m0 + rr;
            float4 v = make_float4(0.f, 0.f, 0.f, 0.f);
            if (m < M) v = *(const float4*)(A + (size_t)m * 128 + kc + kq * 4);
            As[kq * 4 + 0][rr] = v.x;
            As[kq * 4 + 1][rr] = v.y;
            As[kq * 4 + 2][rr] = v.z;
            As[kq * 4 + 3][rr] = v.w;
        }
        #pragma unroll
        for (int it = 0; it < 2; it++) {
            int kk = kb + it * 16;
            *(float4*)&Bs[kk][c4 * 4] =
                *(const float4*)(B + (size_t)(kc + kk) * Ncols + n0 + c4 * 4);
        }
        __syncthreads();
        #pragma unroll
        for (int k = 0; k < 32; k++) {
            float4 a = *(float4*)&As[k][tm * 4];
            float4 b = *(float4*)&Bs[k][tn * 4];
            acc[0][0] += a.x * b.x; acc[0][1] += a.x * b.y; acc[0][2] += a.x * b.z; acc[0][3] += a.x * b.w;
            acc[1][0] += a.y * b.x; acc[1][1] += a.y * b.y; acc[1][2] += a.y * b.z; acc[1][3] += a.y * b.w;
            acc[2][0] += a.z * b.x; acc[2][1] += a.z * b.y; acc[2][2] += a.z * b.z; acc[2][3] += a.z * b.w;
            acc[3][0] += a.w * b.x; acc[3][1] += a.w * b.y; acc[3][2] += a.w * b.z; acc[3][3] += a.w * b.w;
        }
        __syncthreads();
    }
    #pragma unroll
    for (int i = 0; i < 4; i++) {
        int m = m0 + tm * 4 + i;
        if (m < M) {
            float4 o = make_float4(acc[i][0], acc[i][1], acc[i][2], acc[i][3]);
            *(float4*)(C + (size_t)m * Ncols + n0 + tn * 4) = o;
        }
    }
}

// ---------------- layer1 node prep: a_src/a_dst, s1 = p_self, agg1 = 0 ----------------
__global__ void __launch_bounds__(256) node_prep1(const float* __restrict__ att_src,
                                                  const float* __restrict__ att_dst,
                                                  int n) {
    int w = (blockIdx.x * blockDim.x + threadIdx.x) >> 5;
    int lane = threadIdx.x & 31;
    if (w >= n) return;
    float4 hv = *(const float4*)&g_h1[(size_t)w * 128 + lane * 4];
    int head = lane >> 2, sub = lane & 3;
    float4 s4 = *(const float4*)&att_src[head * 16 + sub * 4];
    float4 d4 = *(const float4*)&att_dst[head * 16 + sub * 4];
    float ps = hv.x * s4.x + hv.y * s4.y + hv.z * s4.z + hv.w * s4.w;
    float pd = hv.x * d4.x + hv.y * d4.y + hv.z * d4.z + hv.w * d4.w;
    ps += __shfl_xor_sync(0xffffffffu, ps, 1);
    ps += __shfl_xor_sync(0xffffffffu, ps, 2);
    pd += __shfl_xor_sync(0xffffffffu, pd, 1);
    pd += __shfl_xor_sync(0xffffffffu, pd, 2);
    if (sub == 0) {
        g_asrc1[w * 8 + head] = ps;
        g_adst1[w * 8 + head] = pd;
        g_s1[w * 8 + head] = lrelu_exp(ps + pd);   // self-loop term seeds the denominator
    }
    *(float4*)&g_agg1[(size_t)w * 128 + lane * 4] = make_float4(0.f, 0.f, 0.f, 0.f);
}

// ---------------- layer1 edge pass A: p = exp(lrelu), accumulate denominators --------
__global__ void __launch_bounds__(256) edge_att1(const int* __restrict__ src,
                                                 const int* __restrict__ dst, int E) {
    int e = blockIdx.x * blockDim.x + threadIdx.x;
    if (e >= E) return;
    int s = src[e], d = dst[e];
    float4 as0 = *(const float4*)&g_asrc1[s * 8];
    float4 as1 = *(const float4*)&g_asrc1[s * 8 + 4];
    float4 ad0 = *(const float4*)&g_adst1[d * 8];
    float4 ad1 = *(const float4*)&g_adst1[d * 8 + 4];
    float4 p0, p1;
    p0.x = lrelu_exp(as0.x + ad0.x); p0.y = lrelu_exp(as0.y + ad0.y);
    p0.z = lrelu_exp(as0.z + ad0.z); p0.w = lrelu_exp(as0.w + ad0.w);
    p1.x = lrelu_exp(as1.x + ad1.x); p1.y = lrelu_exp(as1.y + ad1.y);
    p1.z = lrelu_exp(as1.z + ad1.z); p1.w = lrelu_exp(as1.w + ad1.w);
    *(float4*)&g_p1[(size_t)e * 8] = p0;
    *(float4*)&g_p1[(size_t)e * 8 + 4] = p1;
    red4(&g_s1[d * 8], p0);
    red4(&g_s1[d * 8 + 4], p1);
}

// ---------------- layer1 edge pass B: weighted message aggregation -------------------
__global__ void __launch_bounds__(256) edge_agg1(const int* __restrict__ src,
                                                 const int* __restrict__ dst, int E) {
    int t = blockIdx.x * blockDim.x + threadIdx.x;
    int e = t >> 3;
    if (e >= E) return;
    int h = t & 7;
    int s = src[e], d = dst[e];
    float p = g_p1[(size_t)e * 8 + h];
    float alpha = __fdividef(p, g_s1[d * 8 + h] + 1e-16f);
    const float4* hp = (const float4*)&g_h1[(size_t)s * 128 + h * 16];
    float* op = &g_agg1[(size_t)d * 128 + h * 16];
    #pragma unroll
    for (int j = 0; j < 4; j++) {
        float4 v = hp[j];
        v.x *= alpha; v.y *= alpha; v.z *= alpha; v.w *= alpha;
        red4(op + j * 4, v);
    }
}

// ---------------- layer1 finalize: + self msg + bias + residual, LN, ELU -> d_out ----
__global__ void __launch_bounds__(256) node_fin1(const float* __restrict__ bias1,
                                                 const float* __restrict__ gamma,
                                                 const float* __restrict__ beta,
                                                 float* __restrict__ out, int n) {
    int w = (blockIdx.x * blockDim.x + threadIdx.x) >> 5;
    int lane = threadIdx.x & 31;
    if (w >= n) return;
    int head = lane >> 2;
    float4 agg = *(const float4*)&g_agg1[(size_t)w * 128 + lane * 4];
    float4 h1v = *(const float4*)&g_h1[(size_t)w * 128 + lane * 4];
    float4 rv  = *(const float4*)&g_res[(size_t)w * 128 + lane * 4];
    float4 bv  = *(const float4*)&bias1[lane * 4];
    float as = g_asrc1[w * 8 + head], ad = g_adst1[w * 8 + head];
    float pself = lrelu_exp(as + ad);
    float alpha = __fdividef(pself, g_s1[w * 8 + head] + 1e-16f);
    float4 v;
    v.x = agg.x + h1v.x * alpha + bv.x + rv.x;
    v.y = agg.y + h1v.y * alpha + bv.y + rv.y;
    v.z = agg.z + h1v.z * alpha + bv.z + rv.z;
    v.w = agg.w + h1v.w * alpha + bv.w + rv.w;
    float mu = warp_sum(v.x + v.y + v.z + v.w) * (1.0f / 128.0f);
    float dx = v.x - mu, dy = v.y - mu, dz = v.z - mu, dw = v.w - mu;
    float var = warp_sum(dx * dx + dy * dy + dz * dz + dw * dw) * (1.0f / 128.0f);
    float rs = rsqrtf(var + 1e-5f);
    float4 g4 = *(const float4*)&gamma[lane * 4];
    float4 b4 = *(const float4*)&beta[lane * 4];
    float4 o;
    o.x = dx * rs * g4.x + b4.x;
    o.y = dy * rs * g4.y + b4.y;
    o.z = dz * rs * g4.z + b4.z;
    o.w = dw * rs * g4.w + b4.w;
    o.x = o.x > 0.f ? o.x : expm1f(o.x);
    o.y = o.y > 0.f ? o.y : expm1f(o.y);
    o.z = o.z > 0.f ? o.z : expm1f(o.z);
    o.w = o.w > 0.f ? o.w : expm1f(o.w);
    *(float4*)(out + (size_t)w * 128 + lane * 4) = o;
}

// ---------------- layer2 node prep -----------------------------------------------
__global__ void __launch_bounds__(256) node_prep2(const float* __restrict__ att_src,
                                                  const float* __restrict__ att_dst,
                                                  const float* __restrict__ bias2,
                                                  int n) {
    int w = (blockIdx.x * blockDim.x + threadIdx.x) >> 5;
    int lane = threadIdx.x & 31;
    if (w >= n) return;
    float ps = 0.f, pd = 0.f;
    if (lane < 16) {
        float4 hv = *(const float4*)&g_h2[(size_t)w * 64 + lane * 4];
        float4 s4 = *(const float4*)&att_src[lane * 4];
        float4 d4 = *(const float4*)&att_dst[lane * 4];
        ps = hv.x * s4.x + hv.y * s4.y + hv.z * s4.z + hv.w * s4.w;
        pd = hv.x * d4.x + hv.y * d4.y + hv.z * d4.z + hv.w * d4.w;
    }
    #pragma unroll
    for (int o = 8; o > 0; o >>= 1) {
        ps += __shfl_xor_sync(0xffffffffu, ps, o);
        pd += __shfl_xor_sync(0xffffffffu, pd, o);
    }
    if (lane == 0) {
        g_asrc2[w] = ps;
        g_adst2[w] = pd;
        g_s2[w] = lrelu_exp(ps + pd);
    }
    if (lane < 16)
        *(float4*)&g_agg2[(size_t)w * 64 + lane * 4] = *(const float4*)&bias2[lane * 4];
}

// ---------------- layer2 edge pass A ----------------------------------------------
__global__ void __launch_bounds__(256) edge_att2(const int* __restrict__ src,
                                                 const int* __restrict__ dst, int E) {
    int e = blockIdx.x * blockDim.x + threadIdx.x;
    if (e >= E) return;
    int s = src[e], d = dst[e];
    float p = lrelu_exp(g_asrc2[s] + g_adst2[d]);
    g_p2[e] = p;
    atomicAdd(&g_s2[d], p);
}

// ---------------- layer2 edge pass B ----------------------------------------------
__global__ void __launch_bounds__(256) edge_agg2(const int* __restrict__ src,
                                                 const int* __restrict__ dst, int E) {
    int t = blockIdx.x * blockDim.x + threadIdx.x;
    int e = t >> 4;
    if (e >= E) return;
    int c = t & 15;
    int s = src[e], d = dst[e];
    float alpha = __fdividef(g_p2[e], g_s2[d] + 1e-16f);
    float4 v = *(const float4*)&g_h2[(size_t)s * 64 + c * 4];
    v.x *= alpha; v.y *= alpha; v.z *= alpha; v.w *= alpha;
    red4(&g_agg2[(size_t)d * 64 + c * 4], v);
}

// ---------------- layer2 finalize -> logits region of d_out ----------------------
__global__ void __launch_bounds__(256) node_fin2(float* __restrict__ out, int n) {
    int t = blockIdx.x * blockDim.x + threadIdx.x;
    int w = t >> 5;
    int lane = threadIdx.x & 31;
    int i = w * 2 + (lane >> 4);
    if (i >= n) return;
    int c = lane & 15;
    float pself = lrelu_exp(g_asrc2[i] + g_adst2[i]);
    float alpha = __fdividef(pself, g_s2[i] + 1e-16f);
    float4 hv = *(const float4*)&g_h2[(size_t)i * 64 + c * 4];
    float4 a  = *(const float4*)&g_agg2[(size_t)i * 64 + c * 4];
    a.x += hv.x * alpha; a.y += hv.y * alpha; a.z += hv.z * alpha; a.w += hv.w * alpha;
    *(float4*)(out + (size_t)n * 128 + (size_t)i * 64 + c * 4) = a;
}

// ---------------- launch -----------------------------------------------------------
extern "C" void kernel_launch(void* const* d_in, const int* in_sizes, int n_in,
                              void* d_out, int out_size) {
    const float* x        = (const float*)d_in[0];
    const int*   ei       = (const int*)d_in[1];
    const float* W1       = (const float*)d_in[2];
    const float* att_src1 = (const float*)d_in[3];
    const float* att_dst1 = (const float*)d_in[4];
    const float* bias1    = (const float*)d_in[5];
    const float* res_W    = (const float*)d_in[6];
    const float* gamma    = (const float*)d_in[7];
    const float* beta     = (const float*)d_in[8];
    const float* W2       = (const float*)d_in[9];
    const float* att_src2 = (const float*)d_in[10];
    const float* att_dst2 = (const float*)d_in[11];
    const float* bias2    = (const float*)d_in[12];
    float* out = (float*)d_out;

    int n = in_sizes[0] / 128;
    int E = in_sizes[1] / 2;
    if (n > NN) n = NN;
    if (E > EE) E = EE;
    const int* srcp = ei;
    const int* dstp = ei + E;

    float *p_h1, *p_res, *p_h2;
    cudaGetSymbolAddress((void**)&p_h1, g_h1);
    cudaGetSymbolAddress((void**)&p_res, g_res);
    cudaGetSymbolAddress((void**)&p_h2, g_h2);

    dim3 gg1((n + 63) / 64, 2);
    gemm_k128<<<gg1, 256>>>(x, W1, p_h1, n, 128);
    gemm_k128<<<gg1, 256>>>(x, res_W, p_res, n, 128);

    int nwarp_blocks = (n + 7) / 8;
    node_prep1<<<nwarp_blocks, 256>>>(att_src1, att_dst1, n);

    edge_att1<<<(E + 255) / 256, 256>>>(srcp, dstp, E);
    edge_agg1<<<(E * 8 + 255) / 256, 256>>>(srcp, dstp, E);
    node_fin1<<<nwarp_blocks, 256>>>(bias1, gamma, beta, out, n);

    dim3 gg2((n + 63) / 64, 1);
    gemm_k128<<<gg2, 256>>>(out, W2, p_h2, n, 64);
    node_prep2<<<nwarp_blocks, 256>>>(att_src2, att_dst2, bias2, n);

    edge_att2<<<(E + 255) / 256, 256>>>(srcp, dstp, E);
    edge_agg2<<<(E * 16 + 255) / 256, 256>>>(srcp, dstp, E);
    node_fin2<<<(n + 15) / 16, 256>>>(out, n);
}

// round 3
// speedup vs baseline: 1.0394x; 1.0394x over previous
#include <cuda_runtime.h>
#include <math.h>

#define NN 100000
#define EE 1600000

// ---------------- static scratch ----------------
__device__ float g_h1[NN * 128];     // x @ W1
__device__ float g_res[NN * 128];    // x @ res_W
__device__ float g_agg1[NN * 128];   // layer1 unnormalized aggregation
__device__ float g_asrc1[NN * 8];
__device__ float g_adst1[NN * 8];
__device__ float g_s1[NN * 8];       // softmax denominators (seeded with p_self)
__device__ float g_h2[NN * 64];      // h @ W2
__device__ float g_agg2[NN * 64];
__device__ float g_asrc2[NN];
__device__ float g_adst2[NN];
__device__ float g_s2[NN];
__device__ float g_wcat[128 * 256];  // [W1 | res_W]

// ---------------- helpers ----------------
__device__ __forceinline__ void red4(float* p, float4 v) {
    asm volatile("red.global.add.v4.f32 [%0], {%1,%2,%3,%4};"
                 :: "l"(p), "f"(v.x), "f"(v.y), "f"(v.z), "f"(v.w) : "memory");
}
__device__ __forceinline__ void red1(float* p, float v) {
    asm volatile("red.global.add.f32 [%0], %1;" :: "l"(p), "f"(v) : "memory");
}
__device__ __forceinline__ float lrelu_exp(float v) {
    float e = v > 0.0f ? v : 0.2f * v;
    return __expf(e);
}
__device__ __forceinline__ float warp_sum(float v) {
    #pragma unroll
    for (int o = 16; o > 0; o >>= 1) v += __shfl_xor_sync(0xffffffffu, v, o);
    return v;
}

// ---------------- build concatenated weights [128 x 256] ----------------
__global__ void build_wcat(const float* __restrict__ W1, const float* __restrict__ resW) {
    int k = blockIdx.x, c = threadIdx.x;   // 128 blocks x 128 threads
    g_wcat[k * 256 + c] = W1[k * 128 + c];
    g_wcat[k * 256 + 128 + c] = resW[k * 128 + c];
}

// ---------------- SGEMM: C = A[M,128] @ B[128,*], BM=128, BK=8, 8x8 microtiles ------
// blockIdx.y selects the BN-column slab of B; output goes to C0 (y=0) or C1 (y=1).
template<int BN, int NT>
__global__ void __launch_bounds__(NT) sgemm(const float* __restrict__ A,
                                            const float* __restrict__ Bm,
                                            float* __restrict__ C0,
                                            float* __restrict__ C1,
                                            int M, int ldb, int ldc) {
    constexpr int BM = 128, BK = 8, TM = 8, TN = 8;
    static_assert((BN / TN) * (BM / TM) == NT, "thread count");
    static_assert((BK * BN) / (4 * NT) == 1, "B load");
    constexpr int AF4 = (BM * BK) / (4 * NT);

    __shared__ float As[BK][BM + 4];
    __shared__ float Bs[BK][BN];

    const int tid = threadIdx.x;
    const int tx = tid % (BN / TN);
    const int ty = tid / (BN / TN);
    const int m0 = blockIdx.x * BM;
    const int n0 = blockIdx.y * BN;

    const int bkrow = tid / (BN / 4);
    const int bcol  = (tid % (BN / 4)) * 4;

    float acc[TM][TN] = {};

    for (int kc = 0; kc < 128; kc += BK) {
        #pragma unroll
        for (int i = 0; i < AF4; i++) {
            int lin = tid + i * NT;
            int row = lin >> 1;
            int kq  = (lin & 1) * 4;
            float4 v = make_float4(0.f, 0.f, 0.f, 0.f);
            int m = m0 + row;
            if (m < M) v = *(const float4*)(A + (size_t)m * 128 + kc + kq);
            As[kq + 0][row] = v.x; As[kq + 1][row] = v.y;
            As[kq + 2][row] = v.z; As[kq + 3][row] = v.w;
        }
        *(float4*)&Bs[bkrow][bcol] =
            *(const float4*)(Bm + (size_t)(kc + bkrow) * ldb + n0 + bcol);
        __syncthreads();
        #pragma unroll
        for (int k = 0; k < BK; k++) {
            float a[TM], b[TN];
            *(float4*)&a[0] = *(float4*)&As[k][ty * TM];
            *(float4*)&a[4] = *(float4*)&As[k][ty * TM + 4];
            *(float4*)&b[0] = *(float4*)&Bs[k][tx * TN];
            *(float4*)&b[4] = *(float4*)&Bs[k][tx * TN + 4];
            #pragma unroll
            for (int i = 0; i < TM; i++)
                #pragma unroll
                for (int j = 0; j < TN; j++)
                    acc[i][j] += a[i] * b[j];
        }
        __syncthreads();
    }

    float* Cp = blockIdx.y ? C1 : C0;
    #pragma unroll
    for (int i = 0; i < TM; i++) {
        int m = m0 + ty * TM + i;
        if (m < M) {
            *(float4*)(Cp + (size_t)m * ldc + tx * TN)     = *(float4*)&acc[i][0];
            *(float4*)(Cp + (size_t)m * ldc + tx * TN + 4) = *(float4*)&acc[i][4];
        }
    }
}

// ---------------- layer1 node prep: a_src/a_dst, s1 = p_self, agg1 = 0 --------------
__global__ void __launch_bounds__(256) node_prep1(const float* __restrict__ att_src,
                                                  const float* __restrict__ att_dst,
                                                  int n) {
    int w = (blockIdx.x * blockDim.x + threadIdx.x) >> 5;
    int lane = threadIdx.x & 31;
    if (w >= n) return;
    float4 hv = *(const float4*)&g_h1[(size_t)w * 128 + lane * 4];
    int head = lane >> 2, sub = lane & 3;
    float4 s4 = *(const float4*)&att_src[head * 16 + sub * 4];
    float4 d4 = *(const float4*)&att_dst[head * 16 + sub * 4];
    float ps = hv.x * s4.x + hv.y * s4.y + hv.z * s4.z + hv.w * s4.w;
    float pd = hv.x * d4.x + hv.y * d4.y + hv.z * d4.z + hv.w * d4.w;
    ps += __shfl_xor_sync(0xffffffffu, ps, 1);
    ps += __shfl_xor_sync(0xffffffffu, ps, 2);
    pd += __shfl_xor_sync(0xffffffffu, pd, 1);
    pd += __shfl_xor_sync(0xffffffffu, pd, 2);
    if (sub == 0) {
        g_asrc1[w * 8 + head] = ps;
        g_adst1[w * 8 + head] = pd;
        g_s1[w * 8 + head] = lrelu_exp(ps + pd);
    }
    *(float4*)&g_agg1[(size_t)w * 128 + lane * 4] = make_float4(0.f, 0.f, 0.f, 0.f);
}

// ---------------- layer1 merged edge pass: denominators + unnormalized messages -----
__global__ void __launch_bounds__(256) edge1(const int* __restrict__ src,
                                             const int* __restrict__ dst, int E) {
    int t = blockIdx.x * blockDim.x + threadIdx.x;
    int e = t >> 3;
    if (e >= E) return;
    int h = t & 7;
    int s = __ldg(&src[e]), d = __ldg(&dst[e]);
    float p = lrelu_exp(g_asrc1[s * 8 + h] + g_adst1[d * 8 + h]);
    // warp-aggregate 4 p's into one red.v4 on the denominator
    float p1 = __shfl_down_sync(0xffffffffu, p, 1);
    float p2 = __shfl_down_sync(0xffffffffu, p, 2);
    float p3 = __shfl_down_sync(0xffffffffu, p, 3);
    if ((h & 3) == 0)
        red4(&g_s1[d * 8 + h], make_float4(p, p1, p2, p3));
    const float4* hp = (const float4*)&g_h1[(size_t)s * 128 + h * 16];
    float* op = &g_agg1[(size_t)d * 128 + h * 16];
    #pragma unroll
    for (int j = 0; j < 4; j++) {
        float4 v = hp[j];
        v.x *= p; v.y *= p; v.z *= p; v.w *= p;
        red4(op + j * 4, v);
    }
}

// ---------------- layer1 finalize: normalize + self + bias + residual, LN, ELU ------
__global__ void __launch_bounds__(256) node_fin1(const float* __restrict__ bias1,
                                                 const float* __restrict__ gamma,
                                                 const float* __restrict__ beta,
                                                 float* __restrict__ out, int n) {
    int w = (blockIdx.x * blockDim.x + threadIdx.x) >> 5;
    int lane = threadIdx.x & 31;
    if (w >= n) return;
    int head = lane >> 2;
    float4 agg = *(const float4*)&g_agg1[(size_t)w * 128 + lane * 4];
    float4 h1v = *(const float4*)&g_h1[(size_t)w * 128 + lane * 4];
    float4 rv  = *(const float4*)&g_res[(size_t)w * 128 + lane * 4];
    float4 bv  = *(const float4*)&bias1[lane * 4];
    float as = g_asrc1[w * 8 + head], ad = g_adst1[w * 8 + head];
    float pself = lrelu_exp(as + ad);
    float inv = __fdividef(1.0f, g_s1[w * 8 + head] + 1e-16f);
    float4 v;
    v.x = (agg.x + h1v.x * pself) * inv + bv.x + rv.x;
    v.y = (agg.y + h1v.y * pself) * inv + bv.y + rv.y;
    v.z = (agg.z + h1v.z * pself) * inv + bv.z + rv.z;
    v.w = (agg.w + h1v.w * pself) * inv + bv.w + rv.w;
    float mu = warp_sum(v.x + v.y + v.z + v.w) * (1.0f / 128.0f);
    float dx = v.x - mu, dy = v.y - mu, dz = v.z - mu, dw = v.w - mu;
    float var = warp_sum(dx * dx + dy * dy + dz * dz + dw * dw) * (1.0f / 128.0f);
    float rs = rsqrtf(var + 1e-5f);
    float4 g4 = *(const float4*)&gamma[lane * 4];
    float4 b4 = *(const float4*)&beta[lane * 4];
    float4 o;
    o.x = dx * rs * g4.x + b4.x;
    o.y = dy * rs * g4.y + b4.y;
    o.z = dz * rs * g4.z + b4.z;
    o.w = dw * rs * g4.w + b4.w;
    o.x = o.x > 0.f ? o.x : expm1f(o.x);
    o.y = o.y > 0.f ? o.y : expm1f(o.y);
    o.z = o.z > 0.f ? o.z : expm1f(o.z);
    o.w = o.w > 0.f ? o.w : expm1f(o.w);
    *(float4*)(out + (size_t)w * 128 + lane * 4) = o;
}

// ---------------- layer2 node prep -----------------------------------------------
__global__ void __launch_bounds__(256) node_prep2(const float* __restrict__ att_src,
                                                  const float* __restrict__ att_dst,
                                                  int n) {
    int w = (blockIdx.x * blockDim.x + threadIdx.x) >> 5;
    int lane = threadIdx.x & 31;
    if (w >= n) return;
    float ps = 0.f, pd = 0.f;
    if (lane < 16) {
        float4 hv = *(const float4*)&g_h2[(size_t)w * 64 + lane * 4];
        float4 s4 = *(const float4*)&att_src[lane * 4];
        float4 d4 = *(const float4*)&att_dst[lane * 4];
        ps = hv.x * s4.x + hv.y * s4.y + hv.z * s4.z + hv.w * s4.w;
        pd = hv.x * d4.x + hv.y * d4.y + hv.z * d4.z + hv.w * d4.w;
    }
    #pragma unroll
    for (int o = 8; o > 0; o >>= 1) {
        ps += __shfl_xor_sync(0xffffffffu, ps, o);
        pd += __shfl_xor_sync(0xffffffffu, pd, o);
    }
    if (lane == 0) {
        g_asrc2[w] = ps;
        g_adst2[w] = pd;
        g_s2[w] = lrelu_exp(ps + pd);
    }
    if (lane < 16)
        *(float4*)&g_agg2[(size_t)w * 64 + lane * 4] = make_float4(0.f, 0.f, 0.f, 0.f);
}

// ---------------- layer2 merged edge pass -----------------------------------------
__global__ void __launch_bounds__(256) edge2(const int* __restrict__ src,
                                             const int* __restrict__ dst, int E) {
    int t = blockIdx.x * blockDim.x + threadIdx.x;
    int e = t >> 4;
    if (e >= E) return;
    int c = t & 15;
    int s = __ldg(&src[e]), d = __ldg(&dst[e]);
    float p = lrelu_exp(g_asrc2[s] + g_adst2[d]);
    if (c == 0) red1(&g_s2[d], p);
    float4 v = *(const float4*)&g_h2[(size_t)s * 64 + c * 4];
    v.x *= p; v.y *= p; v.z *= p; v.w *= p;
    red4(&g_agg2[(size_t)d * 64 + c * 4], v);
}

// ---------------- layer2 finalize -> logits region of d_out ----------------------
__global__ void __launch_bounds__(256) node_fin2(const float* __restrict__ bias2,
                                                 float* __restrict__ out, int n) {
    int t = blockIdx.x * blockDim.x + threadIdx.x;
    int w = t >> 5;
    int lane = threadIdx.x & 31;
    int i = w * 2 + (lane >> 4);
    if (i >= n) return;
    int c = lane & 15;
    float pself = lrelu_exp(g_asrc2[i] + g_adst2[i]);
    float inv = __fdividef(1.0f, g_s2[i] + 1e-16f);
    float4 hv = *(const float4*)&g_h2[(size_t)i * 64 + c * 4];
    float4 a  = *(const float4*)&g_agg2[(size_t)i * 64 + c * 4];
    float4 bv = *(const float4*)&bias2[c * 4];
    a.x = (a.x + hv.x * pself) * inv + bv.x;
    a.y = (a.y + hv.y * pself) * inv + bv.y;
    a.z = (a.z + hv.z * pself) * inv + bv.z;
    a.w = (a.w + hv.w * pself) * inv + bv.w;
    *(float4*)(out + (size_t)n * 128 + (size_t)i * 64 + c * 4) = a;
}

// ---------------- launch -----------------------------------------------------------
extern "C" void kernel_launch(void* const* d_in, const int* in_sizes, int n_in,
                              void* d_out, int out_size) {
    const float* x        = (const float*)d_in[0];
    const int*   ei       = (const int*)d_in[1];
    const float* W1       = (const float*)d_in[2];
    const float* att_src1 = (const float*)d_in[3];
    const float* att_dst1 = (const float*)d_in[4];
    const float* bias1    = (const float*)d_in[5];
    const float* res_W    = (const float*)d_in[6];
    const float* gamma    = (const float*)d_in[7];
    const float* beta     = (const float*)d_in[8];
    const float* W2       = (const float*)d_in[9];
    const float* att_src2 = (const float*)d_in[10];
    const float* att_dst2 = (const float*)d_in[11];
    const float* bias2    = (const float*)d_in[12];
    float* out = (float*)d_out;

    int n = in_sizes[0] / 128;
    int E = in_sizes[1] / 2;
    if (n > NN) n = NN;
    if (E > EE) E = EE;
    const int* srcp = ei;
    const int* dstp = ei + E;

    float *p_h1, *p_res, *p_h2, *p_wcat;
    cudaGetSymbolAddress((void**)&p_h1, g_h1);
    cudaGetSymbolAddress((void**)&p_res, g_res);
    cudaGetSymbolAddress((void**)&p_h2, g_h2);
    cudaGetSymbolAddress((void**)&p_wcat, g_wcat);

    build_wcat<<<128, 128>>>(W1, res_W);

    int mblocks = (n + 127) / 128;
    // layer1: x @ [W1 | res_W]  -> g_h1 (y=0), g_res (y=1)
    sgemm<128, 256><<<dim3(mblocks, 2), 256>>>(x, p_wcat, p_h1, p_res, n, 256, 128);

    int nwarp_blocks = (n + 7) / 8;
    node_prep1<<<nwarp_blocks, 256>>>(att_src1, att_dst1, n);
    edge1<<<(E * 8 + 255) / 256, 256>>>(srcp, dstp, E);
    node_fin1<<<nwarp_blocks, 256>>>(bias1, gamma, beta, out, n);

    // layer2: h @ W2 -> g_h2
    sgemm<64, 128><<<dim3(mblocks, 1), 128>>>(out, W2, p_h2, nullptr, n, 64, 64);
    node_prep2<<<nwarp_blocks, 256>>>(att_src2, att_dst2, n);
    edge2<<<(E * 16 + 255) / 256, 256>>>(srcp, dstp, E);
    node_fin2<<<(n + 15) / 16, 256>>>(bias2, out, n);
}

// round 4
// speedup vs baseline: 1.5878x; 1.5275x over previous
#include <cuda_runtime.h>
#include <math.h>

#define NN 100000
#define EE 1600000

// ---------------- static scratch ----------------
__device__ float g_h1[NN * 128];     // x @ W1
__device__ float g_res[NN * 128];    // x @ res_W
__device__ float g_asrc1[NN * 8];
__device__ float g_adst1[NN * 8];
__device__ float g_h2[NN * 64];      // h @ W2
__device__ float g_asrc2[NN];
__device__ float g_adst2[NN];
__device__ float g_wcat[128 * 256];  // [W1 | res_W]
// CSR
__device__ int g_cnt[NN];
__device__ int g_rowptr[NN + 1];
__device__ int g_cursor[NN];
__device__ int g_blocksums[128];
__device__ int g_csr[EE];

// ---------------- helpers ----------------
__device__ __forceinline__ float lrelu_exp(float v) {
    float e = v > 0.0f ? v : 0.2f * v;
    return __expf(e);
}
__device__ __forceinline__ float warp_sum(float v) {
    #pragma unroll
    for (int o = 16; o > 0; o >>= 1) v += __shfl_xor_sync(0xffffffffu, v, o);
    return v;
}

// ---------------- build concatenated weights [128 x 256] ----------------
__global__ void build_wcat(const float* __restrict__ W1, const float* __restrict__ resW) {
    int k = blockIdx.x, c = threadIdx.x;
    g_wcat[k * 256 + c] = W1[k * 128 + c];
    g_wcat[k * 256 + 128 + c] = resW[k * 128 + c];
}

// ---------------- CSR build --------------------------------------------------------
__global__ void zero_cnt(int n) {
    int i = blockIdx.x * blockDim.x + threadIdx.x;
    if (i < n) g_cnt[i] = 0;
}
__global__ void count_k(const int* __restrict__ dst, int E) {
    int e = blockIdx.x * blockDim.x + threadIdx.x;
    if (e < E) atomicAdd(&g_cnt[dst[e]], 1);
}
__global__ void __launch_bounds__(1024) scan_blk(int n) {
    __shared__ int sm[1024];
    int tid = threadIdx.x;
    int i = blockIdx.x * 1024 + tid;
    int v = (i < n) ? g_cnt[i] : 0;
    sm[tid] = v;
    __syncthreads();
    #pragma unroll
    for (int off = 1; off < 1024; off <<= 1) {
        int t = (tid >= off) ? sm[tid - off] : 0;
        __syncthreads();
        sm[tid] += t;
        __syncthreads();
    }
    if (i < n) g_rowptr[i] = sm[tid] - v;          // partial exclusive
    if (tid == 1023) g_blocksums[blockIdx.x] = sm[1023];
}
__global__ void __launch_bounds__(128) scan_top(int nb) {
    __shared__ int sm[128];
    int tid = threadIdx.x;
    int v = (tid < nb) ? g_blocksums[tid] : 0;
    sm[tid] = v;
    __syncthreads();
    #pragma unroll
    for (int off = 1; off < 128; off <<= 1) {
        int t = (tid >= off) ? sm[tid - off] : 0;
        __syncthreads();
        sm[tid] += t;
        __syncthreads();
    }
    if (tid < nb) g_blocksums[tid] = sm[tid] - v;  // exclusive block offsets
}
__global__ void scan_add(int n, int E) {
    int i = blockIdx.x * blockDim.x + threadIdx.x;
    if (i < n) {
        int r = g_rowptr[i] + g_blocksums[i >> 10];
        g_rowptr[i] = r;
        g_cursor[i] = r;
    }
    if (i == 0) g_rowptr[n] = E;
}
__global__ void scatter_k(const int* __restrict__ src, const int* __restrict__ dst, int E) {
    int e = blockIdx.x * blockDim.x + threadIdx.x;
    if (e < E) {
        int pos = atomicAdd(&g_cursor[dst[e]], 1);
        g_csr[pos] = src[e];
    }
}

// ---------------- SGEMM: C = A[M,128] @ B[128,*], BM=128, BK=8, 8x8 microtiles ------
template<int BN, int NT>
__global__ void __launch_bounds__(NT) sgemm(const float* __restrict__ A,
                                            const float* __restrict__ Bm,
                                            float* __restrict__ C0,
                                            float* __restrict__ C1,
                                            int M, int ldb, int ldc) {
    constexpr int BM = 128, BK = 8, TM = 8, TN = 8;
    static_assert((BN / TN) * (BM / TM) == NT, "thread count");
    static_assert((BK * BN) / (4 * NT) == 1, "B load");
    constexpr int AF4 = (BM * BK) / (4 * NT);

    __shared__ float As[BK][BM + 4];
    __shared__ float Bs[BK][BN];

    const int tid = threadIdx.x;
    const int tx = tid % (BN / TN);
    const int ty = tid / (BN / TN);
    const int m0 = blockIdx.x * BM;
    const int n0 = blockIdx.y * BN;

    const int bkrow = tid / (BN / 4);
    const int bcol  = (tid % (BN / 4)) * 4;

    float acc[TM][TN] = {};

    for (int kc = 0; kc < 128; kc += BK) {
        #pragma unroll
        for (int i = 0; i < AF4; i++) {
            int lin = tid + i * NT;
            int row = lin >> 1;
            int kq  = (lin & 1) * 4;
            float4 v = make_float4(0.f, 0.f, 0.f, 0.f);
            int m = m0 + row;
            if (m < M) v = *(const float4*)(A + (size_t)m * 128 + kc + kq);
            As[kq + 0][row] = v.x; As[kq + 1][row] = v.y;
            As[kq + 2][row] = v.z; As[kq + 3][row] = v.w;
        }
        *(float4*)&Bs[bkrow][bcol] =
            *(const float4*)(Bm + (size_t)(kc + bkrow) * ldb + n0 + bcol);
        __syncthreads();
        #pragma unroll
        for (int k = 0; k < BK; k++) {
            float a[TM], b[TN];
            *(float4*)&a[0] = *(float4*)&As[k][ty * TM];
            *(float4*)&a[4] = *(float4*)&As[k][ty * TM + 4];
            *(float4*)&b[0] = *(float4*)&Bs[k][tx * TN];
            *(float4*)&b[4] = *(float4*)&Bs[k][tx * TN + 4];
            #pragma unroll
            for (int i = 0; i < TM; i++)
                #pragma unroll
                for (int j = 0; j < TN; j++)
                    acc[i][j] += a[i] * b[j];
        }
        __syncthreads();
    }

    float* Cp = blockIdx.y ? C1 : C0;
    #pragma unroll
    for (int i = 0; i < TM; i++) {
        int m = m0 + ty * TM + i;
        if (m < M) {
            *(float4*)(Cp + (size_t)m * ldc + tx * TN)     = *(float4*)&acc[i][0];
            *(float4*)(Cp + (size_t)m * ldc + tx * TN + 4) = *(float4*)&acc[i][4];
        }
    }
}

// ---------------- layer1 node prep: a_src/a_dst ------------------------------------
__global__ void __launch_bounds__(256) node_prep1(const float* __restrict__ att_src,
                                                  const float* __restrict__ att_dst,
                                                  int n) {
    int w = (blockIdx.x * blockDim.x + threadIdx.x) >> 5;
    int lane = threadIdx.x & 31;
    if (w >= n) return;
    float4 hv = *(const float4*)&g_h1[(size_t)w * 128 + lane * 4];
    int head = lane >> 2, sub = lane & 3;
    float4 s4 = *(const float4*)&att_src[head * 16 + sub * 4];
    float4 d4 = *(const float4*)&att_dst[head * 16 + sub * 4];
    float ps = hv.x * s4.x + hv.y * s4.y + hv.z * s4.z + hv.w * s4.w;
    float pd = hv.x * d4.x + hv.y * d4.y + hv.z * d4.z + hv.w * d4.w;
    ps += __shfl_xor_sync(0xffffffffu, ps, 1);
    ps += __shfl_xor_sync(0xffffffffu, ps, 2);
    pd += __shfl_xor_sync(0xffffffffu, pd, 1);
    pd += __shfl_xor_sync(0xffffffffu, pd, 2);
    if (sub == 0) {
        g_asrc1[w * 8 + head] = ps;
        g_adst1[w * 8 + head] = pd;
    }
}

// ---------------- layer1 pull aggregation + finalize (warp per node) ---------------
__global__ void __launch_bounds__(256) agg_fin1(const float* __restrict__ bias1,
                                                const float* __restrict__ gamma,
                                                const float* __restrict__ beta,
                                                float* __restrict__ out, int n) {
    int i = (blockIdx.x * blockDim.x + threadIdx.x) >> 5;
    int lane = threadIdx.x & 31;
    if (i >= n) return;
    int head = lane >> 2;
    float ad = g_adst1[i * 8 + head];

    float4 acc = make_float4(0.f, 0.f, 0.f, 0.f);
    float denom = 0.f;
    int start = g_rowptr[i], end = g_rowptr[i + 1];

    int j = start;
    for (; j + 4 <= end; j += 4) {
        int s0 = g_csr[j], s1 = g_csr[j + 1], s2 = g_csr[j + 2], s3 = g_csr[j + 3];
        float p0 = lrelu_exp(g_asrc1[s0 * 8 + head] + ad);
        float p1 = lrelu_exp(g_asrc1[s1 * 8 + head] + ad);
        float p2 = lrelu_exp(g_asrc1[s2 * 8 + head] + ad);
        float p3 = lrelu_exp(g_asrc1[s3 * 8 + head] + ad);
        float4 v0 = *(const float4*)&g_h1[(size_t)s0 * 128 + lane * 4];
        float4 v1 = *(const float4*)&g_h1[(size_t)s1 * 128 + lane * 4];
        float4 v2 = *(const float4*)&g_h1[(size_t)s2 * 128 + lane * 4];
        float4 v3 = *(const float4*)&g_h1[(size_t)s3 * 128 + lane * 4];
        acc.x += p0 * v0.x + p1 * v1.x + p2 * v2.x + p3 * v3.x;
        acc.y += p0 * v0.y + p1 * v1.y + p2 * v2.y + p3 * v3.y;
        acc.z += p0 * v0.z + p1 * v1.z + p2 * v2.z + p3 * v3.z;
        acc.w += p0 * v0.w + p1 * v1.w + p2 * v2.w + p3 * v3.w;
        denom += p0 + p1 + p2 + p3;
    }
    for (; j < end; j++) {
        int s = g_csr[j];
        float p = lrelu_exp(g_asrc1[s * 8 + head] + ad);
        float4 v = *(const float4*)&g_h1[(size_t)s * 128 + lane * 4];
        acc.x += p * v.x; acc.y += p * v.y; acc.z += p * v.z; acc.w += p * v.w;
        denom += p;
    }
    // self loop
    {
        float p = lrelu_exp(g_asrc1[i * 8 + head] + ad);
        float4 v = *(const float4*)&g_h1[(size_t)i * 128 + lane * 4];
        acc.x += p * v.x; acc.y += p * v.y; acc.z += p * v.z; acc.w += p * v.w;
        denom += p;
    }
    float inv = __fdividef(1.0f, denom + 1e-16f);
    float4 rv = *(const float4*)&g_res[(size_t)i * 128 + lane * 4];
    float4 bv = *(const float4*)&bias1[lane * 4];
    float4 v;
    v.x = acc.x * inv + bv.x + rv.x;
    v.y = acc.y * inv + bv.y + rv.y;
    v.z = acc.z * inv + bv.z + rv.z;
    v.w = acc.w * inv + bv.w + rv.w;
    float mu = warp_sum(v.x + v.y + v.z + v.w) * (1.0f / 128.0f);
    float dx = v.x - mu, dy = v.y - mu, dz = v.z - mu, dw = v.w - mu;
    float var = warp_sum(dx * dx + dy * dy + dz * dz + dw * dw) * (1.0f / 128.0f);
    float rs = rsqrtf(var + 1e-5f);
    float4 g4 = *(const float4*)&gamma[lane * 4];
    float4 b4 = *(const float4*)&beta[lane * 4];
    float4 o;
    o.x = dx * rs * g4.x + b4.x;
    o.y = dy * rs * g4.y + b4.y;
    o.z = dz * rs * g4.z + b4.z;
    o.w = dw * rs * g4.w + b4.w;
    o.x = o.x > 0.f ? o.x : expm1f(o.x);
    o.y = o.y > 0.f ? o.y : expm1f(o.y);
    o.z = o.z > 0.f ? o.z : expm1f(o.z);
    o.w = o.w > 0.f ? o.w : expm1f(o.w);
    *(float4*)(out + (size_t)i * 128 + lane * 4) = o;
}

// ---------------- layer2 node prep -------------------------------------------------
__global__ void __launch_bounds__(256) node_prep2(const float* __restrict__ att_src,
                                                  const float* __restrict__ att_dst,
                                                  int n) {
    int w = (blockIdx.x * blockDim.x + threadIdx.x) >> 5;
    int lane = threadIdx.x & 31;
    if (w >= n) return;
    float ps = 0.f, pd = 0.f;
    if (lane < 16) {
        float4 hv = *(const float4*)&g_h2[(size_t)w * 64 + lane * 4];
        float4 s4 = *(const float4*)&att_src[lane * 4];
        float4 d4 = *(const float4*)&att_dst[lane * 4];
        ps = hv.x * s4.x + hv.y * s4.y + hv.z * s4.z + hv.w * s4.w;
        pd = hv.x * d4.x + hv.y * d4.y + hv.z * d4.z + hv.w * d4.w;
    }
    #pragma unroll
    for (int o = 8; o > 0; o >>= 1) {
        ps += __shfl_xor_sync(0xffffffffu, ps, o);
        pd += __shfl_xor_sync(0xffffffffu, pd, o);
    }
    if (lane == 0) {
        g_asrc2[w] = ps;
        g_adst2[w] = pd;
    }
}

// ---------------- layer2 pull aggregation + finalize (warp per node) ---------------
__global__ void __launch_bounds__(256) agg_fin2(const float* __restrict__ bias2,
                                                float* __restrict__ out, int n) {
    int i = (blockIdx.x * blockDim.x + threadIdx.x) >> 5;
    int lane = threadIdx.x & 31;
    if (i >= n) return;
    float ad = g_adst2[i];

    float2 acc = make_float2(0.f, 0.f);
    float denom = 0.f;
    int start = g_rowptr[i], end = g_rowptr[i + 1];

    int j = start;
    for (; j + 4 <= end; j += 4) {
        int s0 = g_csr[j], s1 = g_csr[j + 1], s2 = g_csr[j + 2], s3 = g_csr[j + 3];
        float p0 = lrelu_exp(g_asrc2[s0] + ad);
        float p1 = lrelu_exp(g_asrc2[s1] + ad);
        float p2 = lrelu_exp(g_asrc2[s2] + ad);
        float p3 = lrelu_exp(g_asrc2[s3] + ad);
        float2 v0 = *(const float2*)&g_h2[(size_t)s0 * 64 + lane * 2];
        float2 v1 = *(const float2*)&g_h2[(size_t)s1 * 64 + lane * 2];
        float2 v2 = *(const float2*)&g_h2[(size_t)s2 * 64 + lane * 2];
        float2 v3 = *(const float2*)&g_h2[(size_t)s3 * 64 + lane * 2];
        acc.x += p0 * v0.x + p1 * v1.x + p2 * v2.x + p3 * v3.x;
        acc.y += p0 * v0.y + p1 * v1.y + p2 * v2.y + p3 * v3.y;
        denom += p0 + p1 + p2 + p3;
    }
    for (; j < end; j++) {
        int s = g_csr[j];
        float p = lrelu_exp(g_asrc2[s] + ad);
        float2 v = *(const float2*)&g_h2[(size_t)s * 64 + lane * 2];
        acc.x += p * v.x; acc.y += p * v.y;
        denom += p;
    }
    {
        float p = lrelu_exp(g_asrc2[i] + ad);
        float2 v = *(const float2*)&g_h2[(size_t)i * 64 + lane * 2];
        acc.x += p * v.x; acc.y += p * v.y;
        denom += p;
    }
    float inv = __fdividef(1.0f, denom + 1e-16f);
    float2 bv = *(const float2*)&bias2[lane * 2];
    float2 o;
    o.x = acc.x * inv + bv.x;
    o.y = acc.y * inv + bv.y;
    *(float2*)(out + (size_t)n * 128 + (size_t)i * 64 + lane * 2) = o;
}

// ---------------- launch -----------------------------------------------------------
extern "C" void kernel_launch(void* const* d_in, const int* in_sizes, int n_in,
                              void* d_out, int out_size) {
    const float* x        = (const float*)d_in[0];
    const int*   ei       = (const int*)d_in[1];
    const float* W1       = (const float*)d_in[2];
    const float* att_src1 = (const float*)d_in[3];
    const float* att_dst1 = (const float*)d_in[4];
    const float* bias1    = (const float*)d_in[5];
    const float* res_W    = (const float*)d_in[6];
    const float* gamma    = (const float*)d_in[7];
    const float* beta     = (const float*)d_in[8];
    const float* W2       = (const float*)d_in[9];
    const float* att_src2 = (const float*)d_in[10];
    const float* att_dst2 = (const float*)d_in[11];
    const float* bias2    = (const float*)d_in[12];
    float* out = (float*)d_out;

    int n = in_sizes[0] / 128;
    int E = in_sizes[1] / 2;
    if (n > NN) n = NN;
    if (E > EE) E = EE;
    const int* srcp = ei;
    const int* dstp = ei + E;

    float *p_h1, *p_res, *p_h2, *p_wcat;
    cudaGetSymbolAddress((void**)&p_h1, g_h1);
    cudaGetSymbolAddress((void**)&p_res, g_res);
    cudaGetSymbolAddress((void**)&p_h2, g_h2);
    cudaGetSymbolAddress((void**)&p_wcat, g_wcat);

    // ---- CSR build (independent of GEMMs) ----
    int nb = (n + 1023) / 1024;
    zero_cnt<<<(n + 255) / 256, 256>>>(n);
    count_k<<<(E + 255) / 256, 256>>>(dstp, E);
    scan_blk<<<nb, 1024>>>(n);
    scan_top<<<1, 128>>>(nb);
    scan_add<<<(n + 255) / 256, 256>>>(n, E);
    scatter_k<<<(E + 255) / 256, 256>>>(srcp, dstp, E);

    // ---- layer 1 ----
    build_wcat<<<128, 128>>>(W1, res_W);
    int mblocks = (n + 127) / 128;
    sgemm<128, 256><<<dim3(mblocks, 2), 256>>>(x, p_wcat, p_h1, p_res, n, 256, 128);

    int nwarp_blocks = (n + 7) / 8;
    node_prep1<<<nwarp_blocks, 256>>>(att_src1, att_dst1, n);
    agg_fin1<<<nwarp_blocks, 256>>>(bias1, gamma, beta, out, n);

    // ---- layer 2 ----
    sgemm<64, 128><<<dim3(mblocks, 1), 128>>>(out, W2, p_h2, nullptr, n, 64, 64);
    node_prep2<<<nwarp_blocks, 256>>>(att_src2, att_dst2, n);
    agg_fin2<<<nwarp_blocks, 256>>>(bias2, out, n);
}

// round 6
// speedup vs baseline: 2.2723x; 1.4311x over previous
#include <cuda_runtime.h>
#include <cuda_bf16.h>
#include <math.h>
#include <stdint.h>

#define NN 100000
#define EE 1600000

// ---------------- static scratch ----------------
__device__ float g_h1[NN * 128];     // x @ W1
__device__ float g_res[NN * 128];    // x @ res_W
__device__ float g_asrc1[NN * 8];
__device__ float g_adst1[NN * 8];
__device__ float g_h2[NN * 64];      // h @ W2
__device__ float g_asrc2[NN];
__device__ float g_adst2[NN];
// bf16 hi/lo weight images, n-major [n][k=128]
__device__ __nv_bfloat16 g_b1hi[256 * 128];
__device__ __nv_bfloat16 g_b1lo[256 * 128];
__device__ __nv_bfloat16 g_b2hi[64 * 128];
__device__ __nv_bfloat16 g_b2lo[64 * 128];
// CSR
__device__ int g_cnt[NN];
__device__ int g_rowptr[NN + 1];
__device__ int g_cursor[NN];
__device__ int g_blocksums[128];
__device__ int g_csr[EE];

// ---------------- generic helpers ----------------
__device__ __forceinline__ float lrelu_exp(float v) {
    float e = v > 0.0f ? v : 0.2f * v;
    return __expf(e);
}
__device__ __forceinline__ float warp_sum(float v) {
    #pragma unroll
    for (int o = 16; o > 0; o >>= 1) v += __shfl_xor_sync(0xffffffffu, v, o);
    return v;
}
__device__ __forceinline__ uint32_t smem_u32(const void* p) {
    uint32_t a;
    asm("{ .reg .u64 t; cvta.to.shared.u64 t, %1; cvt.u32.u64 %0, t; }" : "=r"(a) : "l"(p));
    return a;
}
__device__ __forceinline__ void ldsm4(uint32_t* r, uint32_t addr) {
    asm volatile("ldmatrix.sync.aligned.m8n8.x4.shared.b16 {%0,%1,%2,%3}, [%4];"
                 : "=r"(r[0]), "=r"(r[1]), "=r"(r[2]), "=r"(r[3]) : "r"(addr));
}
__device__ __forceinline__ void mma16816(float* c, const uint32_t* a, uint32_t b0, uint32_t b1) {
    asm volatile(
        "mma.sync.aligned.m16n8k16.row.col.f32.bf16.bf16.f32 "
        "{%0,%1,%2,%3}, {%4,%5,%6,%7}, {%8,%9}, {%0,%1,%2,%3};"
        : "+f"(c[0]), "+f"(c[1]), "+f"(c[2]), "+f"(c[3])
        : "r"(a[0]), "r"(a[1]), "r"(a[2]), "r"(a[3]), "r"(b0), "r"(b1));
}

// ---------------- B image build (hi/lo split, n-major) -----------------------------
__global__ void build_b1(const float* __restrict__ W1, const float* __restrict__ resW) {
    int n = blockIdx.x, k = threadIdx.x;          // 256 x 128
    float w = (n < 128) ? W1[k * 128 + n] : resW[k * 128 + (n - 128)];
    __nv_bfloat16 hi = __float2bfloat16_rn(w);
    __nv_bfloat16 lo = __float2bfloat16_rn(w - __bfloat162float(hi));
    g_b1hi[n * 128 + k] = hi;
    g_b1lo[n * 128 + k] = lo;
}
__global__ void build_b2(const float* __restrict__ W2) {
    int n = blockIdx.x, k = threadIdx.x;          // 64 x 128
    float w = W2[k * 64 + n];
    __nv_bfloat16 hi = __float2bfloat16_rn(w);
    __nv_bfloat16 lo = __float2bfloat16_rn(w - __bfloat162float(hi));
    g_b2hi[n * 128 + k] = hi;
    g_b2lo[n * 128 + k] = lo;
}

// ---------------- HMMA GEMM: C = A[M,128] @ B[128, gridDim.y*64] -------------------
// bf16 hi/lo split, fp32 accumulate. BM=128, BN=64 per CTA, warp grid 4(m) x 2(n),
// warp tile 32x32 (2 m-tiles x 4 n-tiles of m16n8k16).
#define PADE 136   // smem row stride in bf16 elems (272B: 16B-aligned, conflict-free)
#define SMEM_MMA ((128 * PADE * 2 + 64 * PADE * 2) * 2)

__global__ void __launch_bounds__(256) mma_gemm(const float* __restrict__ A,
                                                const __nv_bfloat16* __restrict__ Bhi,
                                                const __nv_bfloat16* __restrict__ Blo,
                                                float* __restrict__ C0,
                                                float* __restrict__ C1,
                                                int M, int ldc) {
    extern __shared__ __nv_bfloat16 smp[];
    __nv_bfloat16* Ah = smp;
    __nv_bfloat16* Al = Ah + 128 * PADE;
    __nv_bfloat16* Bh = Al + 128 * PADE;
    __nv_bfloat16* Bl = Bh + 64 * PADE;
    const uint32_t sbA_hi = smem_u32(Ah), sbA_lo = smem_u32(Al);
    const uint32_t sbB_hi = smem_u32(Bh), sbB_lo = smem_u32(Bl);

    const int tid = threadIdx.x;
    const int wid = tid >> 5, lane = tid & 31;
    const int m0 = blockIdx.x * 128;
    const __nv_bfloat16* bhi = Bhi + (size_t)blockIdx.y * 64 * 128;
    const __nv_bfloat16* blo = Blo + (size_t)blockIdx.y * 64 * 128;

    // load + split-convert A tile (128 x 128 fp32 -> hi/lo bf16)
    #pragma unroll
    for (int it = 0; it < 16; it++) {
        int idx = tid + it * 256;              // 4096 float4 slots
        int row = idx >> 5;
        int colq = (idx & 31) * 4;
        float4 v = make_float4(0.f, 0.f, 0.f, 0.f);
        if (m0 + row < M) v = *(const float4*)(A + (size_t)(m0 + row) * 128 + colq);
        __nv_bfloat16 h0 = __float2bfloat16_rn(v.x), h1 = __float2bfloat16_rn(v.y);
        __nv_bfloat16 h2 = __float2bfloat16_rn(v.z), h3 = __float2bfloat16_rn(v.w);
        __nv_bfloat16 l0 = __float2bfloat16_rn(v.x - __bfloat162float(h0));
        __nv_bfloat16 l1 = __float2bfloat16_rn(v.y - __bfloat162float(h1));
        __nv_bfloat16 l2 = __float2bfloat16_rn(v.z - __bfloat162float(h2));
        __nv_bfloat16 l3 = __float2bfloat16_rn(v.w - __bfloat162float(h3));
        int o = row * PADE + colq;
        *(__nv_bfloat162*)&Ah[o]     = __halves2bfloat162(h0, h1);
        *(__nv_bfloat162*)&Ah[o + 2] = __halves2bfloat162(h2, h3);
        *(__nv_bfloat162*)&Al[o]     = __halves2bfloat162(l0, l1);
        *(__nv_bfloat162*)&Al[o + 2] = __halves2bfloat162(l2, l3);
    }
    // copy B images (64 x 128 bf16 each) into padded smem
    #pragma unroll
    for (int it = 0; it < 4; it++) {
        int idx = tid + it * 256;              // 1024 float4 per image
        int row = idx >> 4;
        int colq = (idx & 15) * 8;
        *(float4*)&Bh[row * PADE + colq] = ((const float4*)bhi)[idx];
        *(float4*)&Bl[row * PADE + colq] = ((const float4*)blo)[idx];
    }
    __syncthreads();

    const int wm = wid >> 1;                   // 0..3
    const int wn = wid & 1;                    // 0..1
    float acc[2][4][4] = {};

    #pragma unroll
    for (int kk = 0; kk < 8; kk++) {
        uint32_t ah[2][4], alr[2][4];
        #pragma unroll
        for (int mt = 0; mt < 2; mt++) {
            uint32_t r = wm * 32 + mt * 16 + (lane & 15);
            uint32_t c = kk * 16 + (lane >> 4) * 8;
            uint32_t off = (r * PADE + c) * 2;
            ldsm4(ah[mt], sbA_hi + off);
            ldsm4(alr[mt], sbA_lo + off);
        }
        uint32_t bh[2][4], bl[2][4];
        #pragma unroll
        for (int ld = 0; ld < 2; ld++) {
            uint32_t nrow = wn * 32 + ld * 16 + ((lane >> 4) & 1) * 8 + (lane & 7);
            uint32_t c = kk * 16 + ((lane >> 3) & 1) * 8;
            uint32_t off = (nrow * PADE + c) * 2;
            ldsm4(bh[ld], sbB_hi + off);
            ldsm4(bl[ld], sbB_lo + off);
        }
        #pragma unroll
        for (int mt = 0; mt < 2; mt++)
            #pragma unroll
            for (int nt = 0; nt < 4; nt++) {
                uint32_t b0h = bh[nt >> 1][(nt & 1) * 2], b1h = bh[nt >> 1][(nt & 1) * 2 + 1];
                uint32_t b0l = bl[nt >> 1][(nt & 1) * 2], b1l = bl[nt >> 1][(nt & 1) * 2 + 1];
                mma16816(acc[mt][nt], ah[mt], b0h, b1h);
                mma16816(acc[mt][nt], ah[mt], b0l, b1l);
                mma16816(acc[mt][nt], alr[mt], b0h, b1h);
            }
    }

    // epilogue
    float* Cp;
    int coloff;
    if (gridDim.y == 1) { Cp = C0; coloff = 0; }
    else if (blockIdx.y < 2) { Cp = C0; coloff = blockIdx.y * 64; }
    else { Cp = C1; coloff = (blockIdx.y - 2) * 64; }

    #pragma unroll
    for (int mt = 0; mt < 2; mt++)
        #pragma unroll
        for (int nt = 0; nt < 4; nt++) {
            int row = m0 + wm * 32 + mt * 16 + (lane >> 2);
            int col = coloff + wn * 32 + nt * 8 + (lane & 3) * 2;
            if (row < M)
                *(float2*)&Cp[(size_t)row * ldc + col] = make_float2(acc[mt][nt][0], acc[mt][nt][1]);
            if (row + 8 < M)
                *(float2*)&Cp[(size_t)(row + 8) * ldc + col] = make_float2(acc[mt][nt][2], acc[mt][nt][3]);
        }
}

// ---------------- CSR build --------------------------------------------------------
__global__ void zero_cnt(int n) {
    int i = blockIdx.x * blockDim.x + threadIdx.x;
    if (i < n) g_cnt[i] = 0;
}
__global__ void count_k(const int* __restrict__ dst, int E) {
    int e = blockIdx.x * blockDim.x + threadIdx.x;
    if (e < E) atomicAdd(&g_cnt[dst[e]], 1);
}
__global__ void __launch_bounds__(1024) scan_blk(int n) {
    __shared__ int sm[1024];
    int tid = threadIdx.x;
    int i = blockIdx.x * 1024 + tid;
    int v = (i < n) ? g_cnt[i] : 0;
    sm[tid] = v;
    __syncthreads();
    #pragma unroll
    for (int off = 1; off < 1024; off <<= 1) {
        int t = (tid >= off) ? sm[tid - off] : 0;
        __syncthreads();
        sm[tid] += t;
        __syncthreads();
    }
    if (i < n) g_rowptr[i] = sm[tid] - v;
    if (tid == 1023) g_blocksums[blockIdx.x] = sm[1023];
}
__global__ void __launch_bounds__(128) scan_top(int nb) {
    __shared__ int sm[128];
    int tid = threadIdx.x;
    int v = (tid < nb) ? g_blocksums[tid] : 0;
    sm[tid] = v;
    __syncthreads();
    #pragma unroll
    for (int off = 1; off < 128; off <<= 1) {
        int t = (tid >= off) ? sm[tid - off] : 0;
        __syncthreads();
        sm[tid] += t;
        __syncthreads();
    }
    if (tid < nb) g_blocksums[tid] = sm[tid] - v;
}
__global__ void scan_add(int n, int E) {
    int i = blockIdx.x * blockDim.x + threadIdx.x;
    if (i < n) {
        int r = g_rowptr[i] + g_blocksums[i >> 10];
        g_rowptr[i] = r;
        g_cursor[i] = r;
    }
    if (i == 0) g_rowptr[n] = E;
}
__global__ void scatter_k(const int* __restrict__ src, const int* __restrict__ dst, int E) {
    int e = blockIdx.x * blockDim.x + threadIdx.x;
    if (e < E) {
        int pos = atomicAdd(&g_cursor[dst[e]], 1);
        g_csr[pos] = src[e];
    }
}

// ---------------- layer1 node prep -------------------------------------------------
__global__ void __launch_bounds__(256) node_prep1(const float* __restrict__ att_src,
                                                  const float* __restrict__ att_dst,
                                                  int n) {
    int w = (blockIdx.x * blockDim.x + threadIdx.x) >> 5;
    int lane = threadIdx.x & 31;
    if (w >= n) return;
    float4 hv = *(const float4*)&g_h1[(size_t)w * 128 + lane * 4];
    int head = lane >> 2, sub = lane & 3;
    float4 s4 = *(const float4*)&att_src[head * 16 + sub * 4];
    float4 d4 = *(const float4*)&att_dst[head * 16 + sub * 4];
    float ps = hv.x * s4.x + hv.y * s4.y + hv.z * s4.z + hv.w * s4.w;
    float pd = hv.x * d4.x + hv.y * d4.y + hv.z * d4.z + hv.w * d4.w;
    ps += __shfl_xor_sync(0xffffffffu, ps, 1);
    ps += __shfl_xor_sync(0xffffffffu, ps, 2);
    pd += __shfl_xor_sync(0xffffffffu, pd, 1);
    pd += __shfl_xor_sync(0xffffffffu, pd, 2);
    if (sub == 0) {
        g_asrc1[w * 8 + head] = ps;
        g_adst1[w * 8 + head] = pd;
    }
}

// ---------------- layer1 pull aggregation + finalize (warp per node) ---------------
__global__ void __launch_bounds__(256) agg_fin1(const float* __restrict__ bias1,
                                                const float* __restrict__ gamma,
                                                const float* __restrict__ beta,
                                                float* __restrict__ out, int n) {
    int i = (blockIdx.x * blockDim.x + threadIdx.x) >> 5;
    int lane = threadIdx.x & 31;
    if (i >= n) return;
    int head = lane >> 2;
    float ad = g_adst1[i * 8 + head];

    float4 acc = make_float4(0.f, 0.f, 0.f, 0.f);
    float denom = 0.f;
    int start = g_rowptr[i], end = g_rowptr[i + 1];

    int j = start;
    for (; j + 4 <= end; j += 4) {
        int s0 = g_csr[j], s1 = g_csr[j + 1], s2 = g_csr[j + 2], s3 = g_csr[j + 3];
        float p0 = lrelu_exp(g_asrc1[s0 * 8 + head] + ad);
        float p1 = lrelu_exp(g_asrc1[s1 * 8 + head] + ad);
        float p2 = lrelu_exp(g_asrc1[s2 * 8 + head] + ad);
        float p3 = lrelu_exp(g_asrc1[s3 * 8 + head] + ad);
        float4 v0 = *(const float4*)&g_h1[(size_t)s0 * 128 + lane * 4];
        float4 v1 = *(const float4*)&g_h1[(size_t)s1 * 128 + lane * 4];
        float4 v2 = *(const float4*)&g_h1[(size_t)s2 * 128 + lane * 4];
        float4 v3 = *(const float4*)&g_h1[(size_t)s3 * 128 + lane * 4];
        acc.x += p0 * v0.x + p1 * v1.x + p2 * v2.x + p3 * v3.x;
        acc.y += p0 * v0.y + p1 * v1.y + p2 * v2.y + p3 * v3.y;
        acc.z += p0 * v0.z + p1 * v1.z + p2 * v2.z + p3 * v3.z;
        acc.w += p0 * v0.w + p1 * v1.w + p2 * v2.w + p3 * v3.w;
        denom += p0 + p1 + p2 + p3;
    }
    for (; j < end; j++) {
        int s = g_csr[j];
        float p = lrelu_exp(g_asrc1[s * 8 + head] + ad);
        float4 v = *(const float4*)&g_h1[(size_t)s * 128 + lane * 4];
        acc.x += p * v.x; acc.y += p * v.y; acc.z += p * v.z; acc.w += p * v.w;
        denom += p;
    }
    {
        float p = lrelu_exp(g_asrc1[i * 8 + head] + ad);
        float4 v = *(const float4*)&g_h1[(size_t)i * 128 + lane * 4];
        acc.x += p * v.x; acc.y += p * v.y; acc.z += p * v.z; acc.w += p * v.w;
        denom += p;
    }
    float inv = __fdividef(1.0f, denom + 1e-16f);
    float4 rv = *(const float4*)&g_res[(size_t)i * 128 + lane * 4];
    float4 bv = *(const float4*)&bias1[lane * 4];
    float4 v;
    v.x = acc.x * inv + bv.x + rv.x;
    v.y = acc.y * inv + bv.y + rv.y;
    v.z = acc.z * inv + bv.z + rv.z;
    v.w = acc.w * inv + bv.w + rv.w;
    float mu = warp_sum(v.x + v.y + v.z + v.w) * (1.0f / 128.0f);
    float dx = v.x - mu, dy = v.y - mu, dz = v.z - mu, dw = v.w - mu;
    float var = warp_sum(dx * dx + dy * dy + dz * dz + dw * dw) * (1.0f / 128.0f);
    float rs = rsqrtf(var + 1e-5f);
    float4 g4 = *(const float4*)&gamma[lane * 4];
    float4 b4 = *(const float4*)&beta[lane * 4];
    float4 o;
    o.x = dx * rs * g4.x + b4.x;
    o.y = dy * rs * g4.y + b4.y;
    o.z = dz * rs * g4.z + b4.z;
    o.w = dw * rs * g4.w + b4.w;
    o.x = o.x > 0.f ? o.x : expm1f(o.x);
    o.y = o.y > 0.f ? o.y : expm1f(o.y);
    o.z = o.z > 0.f ? o.z : expm1f(o.z);
    o.w = o.w > 0.f ? o.w : expm1f(o.w);
    *(float4*)(out + (size_t)i * 128 + lane * 4) = o;
}

// ---------------- layer2 node prep -------------------------------------------------
__global__ void __launch_bounds__(256) node_prep2(const float* __restrict__ att_src,
                                                  const float* __restrict__ att_dst,
                                                  int n) {
    int w = (blockIdx.x * blockDim.x + threadIdx.x) >> 5;
    int lane = threadIdx.x & 31;
    if (w >= n) return;
    float ps = 0.f, pd = 0.f;
    if (lane < 16) {
        float4 hv = *(const float4*)&g_h2[(size_t)w * 64 + lane * 4];
        float4 s4 = *(const float4*)&att_src[lane * 4];
        float4 d4 = *(const float4*)&att_dst[lane * 4];
        ps = hv.x * s4.x + hv.y * s4.y + hv.z * s4.z + hv.w * s4.w;
        pd = hv.x * d4.x + hv.y * d4.y + hv.z * d4.z + hv.w * d4.w;
    }
    #pragma unroll
    for (int o = 8; o > 0; o >>= 1) {
        ps += __shfl_xor_sync(0xffffffffu, ps, o);
        pd += __shfl_xor_sync(0xffffffffu, pd, o);
    }
    if (lane == 0) {
        g_asrc2[w] = ps;
        g_adst2[w] = pd;
    }
}

// ---------------- layer2 pull aggregation + finalize (warp per node) ---------------
__global__ void __launch_bounds__(256) agg_fin2(const float* __restrict__ bias2,
                                                float* __restrict__ out, int n) {
    int i = (blockIdx.x * blockDim.x + threadIdx.x) >> 5;
    int lane = threadIdx.x & 31;
    if (i >= n) return;
    float ad = g_adst2[i];

    float2 acc = make_float2(0.f, 0.f);
    float denom = 0.f;
    int start = g_rowptr[i], end = g_rowptr[i + 1];

    int j = start;
    for (; j + 4 <= end; j += 4) {
        int s0 = g_csr[j], s1 = g_csr[j + 1], s2 = g_csr[j + 2], s3 = g_csr[j + 3];
        float p0 = lrelu_exp(g_asrc2[s0] + ad);
        float p1 = lrelu_exp(g_asrc2[s1] + ad);
        float p2 = lrelu_exp(g_asrc2[s2] + ad);
        float p3 = lrelu_exp(g_asrc2[s3] + ad);
        float2 v0 = *(const float2*)&g_h2[(size_t)s0 * 64 + lane * 2];
        float2 v1 = *(const float2*)&g_h2[(size_t)s1 * 64 + lane * 2];
        float2 v2 = *(const float2*)&g_h2[(size_t)s2 * 64 + lane * 2];
        float2 v3 = *(const float2*)&g_h2[(size_t)s3 * 64 + lane * 2];
        acc.x += p0 * v0.x + p1 * v1.x + p2 * v2.x + p3 * v3.x;
        acc.y += p0 * v0.y + p1 * v1.y + p2 * v2.y + p3 * v3.y;
        denom += p0 + p1 + p2 + p3;
    }
    for (; j < end; j++) {
        int s = g_csr[j];
        float p = lrelu_exp(g_asrc2[s] + ad);
        float2 v = *(const float2*)&g_h2[(size_t)s * 64 + lane * 2];
        acc.x += p * v.x; acc.y += p * v.y;
        denom += p;
    }
    {
        float p = lrelu_exp(g_asrc2[i] + ad);
        float2 v = *(const float2*)&g_h2[(size_t)i * 64 + lane * 2];
        acc.x += p * v.x; acc.y += p * v.y;
        denom += p;
    }
    float inv = __fdividef(1.0f, denom + 1e-16f);
    float2 bv = *(const float2*)&bias2[lane * 2];
    float2 o;
    o.x = acc.x * inv + bv.x;
    o.y = acc.y * inv + bv.y;
    *(float2*)(out + (size_t)n * 128 + (size_t)i * 64 + lane * 2) = o;
}

// ---------------- launch -----------------------------------------------------------
extern "C" void kernel_launch(void* const* d_in, const int* in_sizes, int n_in,
                              void* d_out, int out_size) {
    const float* x        = (const float*)d_in[0];
    const int*   ei       = (const int*)d_in[1];
    const float* W1       = (const float*)d_in[2];
    const float* att_src1 = (const float*)d_in[3];
    const float* att_dst1 = (const float*)d_in[4];
    const float* bias1    = (const float*)d_in[5];
    const float* res_W    = (const float*)d_in[6];
    const float* gamma    = (const float*)d_in[7];
    const float* beta     = (const float*)d_in[8];
    const float* W2       = (const float*)d_in[9];
    const float* att_src2 = (const float*)d_in[10];
    const float* att_dst2 = (const float*)d_in[11];
    const float* bias2    = (const float*)d_in[12];
    float* out = (float*)d_out;

    int n = in_sizes[0] / 128;
    int E = in_sizes[1] / 2;
    if (n > NN) n = NN;
    if (E > EE) E = EE;
    const int* srcp = ei;
    const int* dstp = ei + E;

    float *p_h1, *p_res, *p_h2;
    __nv_bfloat16 *b1h, *b1l, *b2h, *b2l;
    cudaGetSymbolAddress((void**)&p_h1, g_h1);
    cudaGetSymbolAddress((void**)&p_res, g_res);
    cudaGetSymbolAddress((void**)&p_h2, g_h2);
    cudaGetSymbolAddress((void**)&b1h, g_b1hi);
    cudaGetSymbolAddress((void**)&b1l, g_b1lo);
    cudaGetSymbolAddress((void**)&b2h, g_b2hi);
    cudaGetSymbolAddress((void**)&b2l, g_b2lo);

    cudaFuncSetAttribute(mma_gemm, cudaFuncAttributeMaxDynamicSharedMemorySize, SMEM_MMA);

    // ---- CSR build ----
    int nb = (n + 1023) / 1024;
    zero_cnt<<<(n + 255) / 256, 256>>>(n);
    count_k<<<(E + 255) / 256, 256>>>(dstp, E);
    scan_blk<<<nb, 1024>>>(n);
    scan_top<<<1, 128>>>(nb);
    scan_add<<<(n + 255) / 256, 256>>>(n, E);
    scatter_k<<<(E + 255) / 256, 256>>>(srcp, dstp, E);

    // ---- layer 1: HMMA GEMM  [h1 | res] = x @ [W1 | res_W] ----
    build_b1<<<256, 128>>>(W1, res_W);
    int mblocks = (n + 127) / 128;
    mma_gemm<<<dim3(mblocks, 4), 256, SMEM_MMA>>>(x, b1h, b1l, p_h1, p_res, n, 128);

    int nwarp_blocks = (n + 7) / 8;
    node_prep1<<<nwarp_blocks, 256>>>(att_src1, att_dst1, n);
    agg_fin1<<<nwarp_blocks, 256>>>(bias1, gamma, beta, out, n);

    // ---- layer 2: HMMA GEMM  h2 = h @ W2 ----
    build_b2<<<64, 128>>>(W2);
    mma_gemm<<<dim3(mblocks, 1), 256, SMEM_MMA>>>(out, b2h, b2l, p_h2, nullptr, n, 64);

    node_prep2<<<nwarp_blocks, 256>>>(att_src2, att_dst2, n);
    agg_fin2<<<nwarp_blocks, 256>>>(bias2, out, n);
}

// round 7
// speedup vs baseline: 2.3599x; 1.0386x over previous
#include <cuda_runtime.h>
#include <cuda_bf16.h>
#include <math.h>
#include <stdint.h>

#define NN 100000
#define EE 1600000

// ---------------- static scratch ----------------
__device__ float g_h1[NN * 128];     // x @ W1
__device__ float g_res[NN * 128];    // x @ res_W
__device__ float g_asrc1[NN * 8];
__device__ float g_adst1[NN * 8];
__device__ float g_h2[NN * 64];      // h @ W2
__device__ float g_asrc2[NN];
__device__ float g_adst2[NN];
// bf16 hi/lo weight images, n-major [n][k=128]
__device__ __nv_bfloat16 g_b1hi[256 * 128];
__device__ __nv_bfloat16 g_b1lo[256 * 128];
__device__ __nv_bfloat16 g_b2hi[64 * 128];
__device__ __nv_bfloat16 g_b2lo[64 * 128];
// CSR
__device__ int g_cnt[NN];
__device__ int g_rowptr[NN + 1];
__device__ int g_cursor[NN];
__device__ int g_blocksums[128];
__device__ int g_csr[EE];

// ---------------- generic helpers ----------------
__device__ __forceinline__ float lrelu_exp(float v) {
    float e = v > 0.0f ? v : 0.2f * v;
    return __expf(e);
}
__device__ __forceinline__ float warp_sum(float v) {
    #pragma unroll
    for (int o = 16; o > 0; o >>= 1) v += __shfl_xor_sync(0xffffffffu, v, o);
    return v;
}
__device__ __forceinline__ uint32_t smem_u32(const void* p) {
    uint32_t a;
    asm("{ .reg .u64 t; cvta.to.shared.u64 t, %1; cvt.u32.u64 %0, t; }" : "=r"(a) : "l"(p));
    return a;
}
__device__ __forceinline__ void ldsm4(uint32_t* r, uint32_t addr) {
    asm volatile("ldmatrix.sync.aligned.m8n8.x4.shared.b16 {%0,%1,%2,%3}, [%4];"
                 : "=r"(r[0]), "=r"(r[1]), "=r"(r[2]), "=r"(r[3]) : "r"(addr));
}
__device__ __forceinline__ void mma16816(float* c, const uint32_t* a, uint32_t b0, uint32_t b1) {
    asm volatile(
        "mma.sync.aligned.m16n8k16.row.col.f32.bf16.bf16.f32 "
        "{%0,%1,%2,%3}, {%4,%5,%6,%7}, {%8,%9}, {%0,%1,%2,%3};"
        : "+f"(c[0]), "+f"(c[1]), "+f"(c[2]), "+f"(c[3])
        : "r"(a[0]), "r"(a[1]), "r"(a[2]), "r"(a[3]), "r"(b0), "r"(b1));
}

// ---------------- B image build (hi/lo split, n-major) -----------------------------
__global__ void build_b1(const float* __restrict__ W1, const float* __restrict__ resW) {
    int n = blockIdx.x, k = threadIdx.x;          // 256 x 128
    float w = (n < 128) ? W1[k * 128 + n] : resW[k * 128 + (n - 128)];
    __nv_bfloat16 hi = __float2bfloat16_rn(w);
    __nv_bfloat16 lo = __float2bfloat16_rn(w - __bfloat162float(hi));
    g_b1hi[n * 128 + k] = hi;
    g_b1lo[n * 128 + k] = lo;
}
__global__ void build_b2(const float* __restrict__ W2) {
    int n = blockIdx.x, k = threadIdx.x;          // 64 x 128
    float w = W2[k * 64 + n];
    __nv_bfloat16 hi = __float2bfloat16_rn(w);
    __nv_bfloat16 lo = __float2bfloat16_rn(w - __bfloat162float(hi));
    g_b2hi[n * 128 + k] = hi;
    g_b2lo[n * 128 + k] = lo;
}

// ---------------- HMMA GEMM + fused attention-coefficient epilogue -----------------
// bf16 hi/lo split, fp32 accumulate. BM=128, BN=64 per CTA, warp grid 4(m) x 2(n),
// warp tile 32x32 (2 m-tiles x 4 n-tiles of m16n8k16).
// mode 1: layer-1 (gridDim.y=4; slabs 0,1 -> h1 + per-head att dots; 2,3 -> res)
// mode 2: layer-2 (gridDim.y=1; h2 + single-head att dots via smem reduce)
#define PADE 136   // smem row stride in bf16 elems
#define SMEM_MMA ((128 * PADE * 2 + 64 * PADE * 2) * 2)

__global__ void __launch_bounds__(256) mma_gemm(const float* __restrict__ A,
                                                const __nv_bfloat16* __restrict__ Bhi,
                                                const __nv_bfloat16* __restrict__ Blo,
                                                float* __restrict__ C0,
                                                float* __restrict__ C1,
                                                const float* __restrict__ att_src,
                                                const float* __restrict__ att_dst,
                                                int M, int ldc, int mode) {
    extern __shared__ __nv_bfloat16 smp[];
    __nv_bfloat16* Ah = smp;
    __nv_bfloat16* Al = Ah + 128 * PADE;
    __nv_bfloat16* Bh = Al + 128 * PADE;
    __nv_bfloat16* Bl = Bh + 64 * PADE;
    const uint32_t sbA_hi = smem_u32(Ah), sbA_lo = smem_u32(Al);
    const uint32_t sbB_hi = smem_u32(Bh), sbB_lo = smem_u32(Bl);

    const int tid = threadIdx.x;
    const int wid = tid >> 5, lane = tid & 31;
    const int m0 = blockIdx.x * 128;
    const __nv_bfloat16* bhi = Bhi + (size_t)blockIdx.y * 64 * 128;
    const __nv_bfloat16* blo = Blo + (size_t)blockIdx.y * 64 * 128;

    // load + split-convert A tile (128 x 128 fp32 -> hi/lo bf16)
    #pragma unroll
    for (int it = 0; it < 16; it++) {
        int idx = tid + it * 256;
        int row = idx >> 5;
        int colq = (idx & 31) * 4;
        float4 v = make_float4(0.f, 0.f, 0.f, 0.f);
        if (m0 + row < M) v = *(const float4*)(A + (size_t)(m0 + row) * 128 + colq);
        __nv_bfloat16 h0 = __float2bfloat16_rn(v.x), h1 = __float2bfloat16_rn(v.y);
        __nv_bfloat16 h2 = __float2bfloat16_rn(v.z), h3 = __float2bfloat16_rn(v.w);
        __nv_bfloat16 l0 = __float2bfloat16_rn(v.x - __bfloat162float(h0));
        __nv_bfloat16 l1 = __float2bfloat16_rn(v.y - __bfloat162float(h1));
        __nv_bfloat16 l2 = __float2bfloat16_rn(v.z - __bfloat162float(h2));
        __nv_bfloat16 l3 = __float2bfloat16_rn(v.w - __bfloat162float(h3));
        int o = row * PADE + colq;
        *(__nv_bfloat162*)&Ah[o]     = __halves2bfloat162(h0, h1);
        *(__nv_bfloat162*)&Ah[o + 2] = __halves2bfloat162(h2, h3);
        *(__nv_bfloat162*)&Al[o]     = __halves2bfloat162(l0, l1);
        *(__nv_bfloat162*)&Al[o + 2] = __halves2bfloat162(l2, l3);
    }
    // copy B images (64 x 128 bf16 each) into padded smem
    #pragma unroll
    for (int it = 0; it < 4; it++) {
        int idx = tid + it * 256;
        int row = idx >> 4;
        int colq = (idx & 15) * 8;
        *(float4*)&Bh[row * PADE + colq] = ((const float4*)bhi)[idx];
        *(float4*)&Bl[row * PADE + colq] = ((const float4*)blo)[idx];
    }
    __syncthreads();

    const int wm = wid >> 1;                   // 0..3
    const int wn = wid & 1;                    // 0..1
    float acc[2][4][4] = {};

    #pragma unroll
    for (int kk = 0; kk < 8; kk++) {
        uint32_t ah[2][4], alr[2][4];
        #pragma unroll
        for (int mt = 0; mt < 2; mt++) {
            uint32_t r = wm * 32 + mt * 16 + (lane & 15);
            uint32_t c = kk * 16 + (lane >> 4) * 8;
            uint32_t off = (r * PADE + c) * 2;
            ldsm4(ah[mt], sbA_hi + off);
            ldsm4(alr[mt], sbA_lo + off);
        }
        uint32_t bh[2][4], bl[2][4];
        #pragma unroll
        for (int ld = 0; ld < 2; ld++) {
            uint32_t nrow = wn * 32 + ld * 16 + ((lane >> 4) & 1) * 8 + (lane & 7);
            uint32_t c = kk * 16 + ((lane >> 3) & 1) * 8;
            uint32_t off = (nrow * PADE + c) * 2;
            ldsm4(bh[ld], sbB_hi + off);
            ldsm4(bl[ld], sbB_lo + off);
        }
        #pragma unroll
        for (int mt = 0; mt < 2; mt++)
            #pragma unroll
            for (int nt = 0; nt < 4; nt++) {
                uint32_t b0h = bh[nt >> 1][(nt & 1) * 2], b1h = bh[nt >> 1][(nt & 1) * 2 + 1];
                uint32_t b0l = bl[nt >> 1][(nt & 1) * 2], b1l = bl[nt >> 1][(nt & 1) * 2 + 1];
                mma16816(acc[mt][nt], ah[mt], b0h, b1h);
                mma16816(acc[mt][nt], ah[mt], b0l, b1l);
                mma16816(acc[mt][nt], alr[mt], b0h, b1h);
            }
    }

    // ---- C store ----
    float* Cp;
    int coloff;
    if (gridDim.y == 1) { Cp = C0; coloff = 0; }
    else if (blockIdx.y < 2) { Cp = C0; coloff = blockIdx.y * 64; }
    else { Cp = C1; coloff = (blockIdx.y - 2) * 64; }

    #pragma unroll
    for (int mt = 0; mt < 2; mt++)
        #pragma unroll
        for (int nt = 0; nt < 4; nt++) {
            int row = m0 + wm * 32 + mt * 16 + (lane >> 2);
            int col = coloff + wn * 32 + nt * 8 + (lane & 3) * 2;
            if (row < M)
                *(float2*)&Cp[(size_t)row * ldc + col] = make_float2(acc[mt][nt][0], acc[mt][nt][1]);
            if (row + 8 < M)
                *(float2*)&Cp[(size_t)(row + 8) * ldc + col] = make_float2(acc[mt][nt][2], acc[mt][nt][3]);
        }

    // ---- fused attention-coefficient epilogue ----
    if (mode == 1 && blockIdx.y < 2) {
        // 8 heads x 16 cols; each head entirely inside one warp's 32-col chunk
        #pragma unroll
        for (int mt = 0; mt < 2; mt++) {
            #pragma unroll
            for (int hh = 0; hh < 2; hh++) {
                int head = blockIdx.y * 4 + wn * 2 + hh;
                float ps0 = 0.f, pd0 = 0.f, ps1 = 0.f, pd1 = 0.f;
                #pragma unroll
                for (int q = 0; q < 2; q++) {
                    int nt = hh * 2 + q;
                    int cih = q * 8 + (lane & 3) * 2;
                    float a0 = att_src[head * 16 + cih], a1 = att_src[head * 16 + cih + 1];
                    float d0 = att_dst[head * 16 + cih], d1 = att_dst[head * 16 + cih + 1];
                    ps0 += acc[mt][nt][0] * a0 + acc[mt][nt][1] * a1;
                    pd0 += acc[mt][nt][0] * d0 + acc[mt][nt][1] * d1;
                    ps1 += acc[mt][nt][2] * a0 + acc[mt][nt][3] * a1;
                    pd1 += acc[mt][nt][2] * d0 + acc[mt][nt][3] * d1;
                }
                #pragma unroll
                for (int o = 1; o <= 2; o <<= 1) {
                    ps0 += __shfl_xor_sync(0xffffffffu, ps0, o);
                    pd0 += __shfl_xor_sync(0xffffffffu, pd0, o);
                    ps1 += __shfl_xor_sync(0xffffffffu, ps1, o);
                    pd1 += __shfl_xor_sync(0xffffffffu, pd1, o);
                }
                if ((lane & 3) == 0) {
                    int r0 = m0 + wm * 32 + mt * 16 + (lane >> 2);
                    if (r0 < M)     { g_asrc1[r0 * 8 + head] = ps0;       g_adst1[r0 * 8 + head] = pd0; }
                    if (r0 + 8 < M) { g_asrc1[(r0 + 8) * 8 + head] = ps1; g_adst1[(r0 + 8) * 8 + head] = pd1; }
                }
            }
        }
    }
    if (mode == 2) {
        // one head over 64 cols spanning both warp columns -> smem reduce
        float* sps = (float*)smp;          // [128][2]
        float* spd = sps + 256;            // [128][2]
        float ps[2][2] = {}, pd[2][2] = {};  // [mt][half]
        #pragma unroll
        for (int nt = 0; nt < 4; nt++) {
            int col = wn * 32 + nt * 8 + (lane & 3) * 2;
            float a0 = att_src[col], a1 = att_src[col + 1];
            float d0 = att_dst[col], d1 = att_dst[col + 1];
            #pragma unroll
            for (int mt = 0; mt < 2; mt++) {
                ps[mt][0] += acc[mt][nt][0] * a0 + acc[mt][nt][1] * a1;
                pd[mt][0] += acc[mt][nt][0] * d0 + acc[mt][nt][1] * d1;
                ps[mt][1] += acc[mt][nt][2] * a0 + acc[mt][nt][3] * a1;
                pd[mt][1] += acc[mt][nt][2] * d0 + acc[mt][nt][3] * d1;
            }
        }
        #pragma unroll
        for (int o = 1; o <= 2; o <<= 1)
            #pragma unroll
            for (int mt = 0; mt < 2; mt++)
                #pragma unroll
                for (int hf = 0; hf < 2; hf++) {
                    ps[mt][hf] += __shfl_xor_sync(0xffffffffu, ps[mt][hf], o);
                    pd[mt][hf] += __shfl_xor_sync(0xffffffffu, pd[mt][hf], o);
                }
        __syncthreads();   // all warps done with mainloop smem before reuse
        if ((lane & 3) == 0) {
            #pragma unroll
            for (int mt = 0; mt < 2; mt++)
                #pragma unroll
                for (int hf = 0; hf < 2; hf++) {
                    int rl = wm * 32 + mt * 16 + (lane >> 2) + hf * 8;
                    sps[rl * 2 + wn] = ps[mt][hf];
                    spd[rl * 2 + wn] = pd[mt][hf];
                }
        }
        __syncthreads();
        if (tid < 128) {
            int r = m0 + tid;
            if (r < M) {
                g_asrc2[r] = sps[tid * 2] + sps[tid * 2 + 1];
                g_adst2[r] = spd[tid * 2] + spd[tid * 2 + 1];
            }
        }
    }
}

// ---------------- CSR build --------------------------------------------------------
__global__ void zero_cnt(int n) {
    int i = blockIdx.x * blockDim.x + threadIdx.x;
    if (i < n) g_cnt[i] = 0;
}
__global__ void count_k(const int* __restrict__ dst, int E) {
    int e = blockIdx.x * blockDim.x + threadIdx.x;
    if (e < E) atomicAdd(&g_cnt[dst[e]], 1);
}
__global__ void __launch_bounds__(1024) scan_blk(int n) {
    __shared__ int sm[1024];
    int tid = threadIdx.x;
    int i = blockIdx.x * 1024 + tid;
    int v = (i < n) ? g_cnt[i] : 0;
    sm[tid] = v;
    __syncthreads();
    #pragma unroll
    for (int off = 1; off < 1024; off <<= 1) {
        int t = (tid >= off) ? sm[tid - off] : 0;
        __syncthreads();
        sm[tid] += t;
        __syncthreads();
    }
    if (i < n) g_rowptr[i] = sm[tid] - v;
    if (tid == 1023) g_blocksums[blockIdx.x] = sm[1023];
}
__global__ void __launch_bounds__(128) scan_top(int nb) {
    __shared__ int sm[128];
    int tid = threadIdx.x;
    int v = (tid < nb) ? g_blocksums[tid] : 0;
    sm[tid] = v;
    __syncthreads();
    #pragma unroll
    for (int off = 1; off < 128; off <<= 1) {
        int t = (tid >= off) ? sm[tid - off] : 0;
        __syncthreads();
        sm[tid] += t;
        __syncthreads();
    }
    if (tid < nb) g_blocksums[tid] = sm[tid] - v;
}
__global__ void scan_add(int n, int E) {
    int i = blockIdx.x * blockDim.x + threadIdx.x;
    if (i < n) {
        int r = g_rowptr[i] + g_blocksums[i >> 10];
        g_rowptr[i] = r;
        g_cursor[i] = r;
    }
    if (i == 0) g_rowptr[n] = E;
}
__global__ void scatter_k(const int* __restrict__ src, const int* __restrict__ dst, int E) {
    int e = blockIdx.x * blockDim.x + threadIdx.x;
    if (e < E) {
        int pos = atomicAdd(&g_cursor[dst[e]], 1);
        g_csr[pos] = src[e];
    }
}

// ---------------- layer1 pull aggregation + finalize (warp per node) ---------------
__global__ void __launch_bounds__(256) agg_fin1(const float* __restrict__ bias1,
                                                const float* __restrict__ gamma,
                                                const float* __restrict__ beta,
                                                float* __restrict__ out, int n) {
    int i = (blockIdx.x * blockDim.x + threadIdx.x) >> 5;
    int lane = threadIdx.x & 31;
    if (i >= n) return;
    int head = lane >> 2;
    float ad = g_adst1[i * 8 + head];

    // self loop (independent of edge loop -> issues early)
    float4 acc;
    float denom;
    {
        float p = lrelu_exp(g_asrc1[i * 8 + head] + ad);
        float4 v = *(const float4*)&g_h1[(size_t)i * 128 + lane * 4];
        acc = make_float4(p * v.x, p * v.y, p * v.z, p * v.w);
        denom = p;
    }
    int start = g_rowptr[i], end = g_rowptr[i + 1];

    int j = start;
    for (; j + 4 <= end; j += 4) {
        int s0 = g_csr[j], s1 = g_csr[j + 1], s2 = g_csr[j + 2], s3 = g_csr[j + 3];
        float p0 = lrelu_exp(g_asrc1[s0 * 8 + head] + ad);
        float p1 = lrelu_exp(g_asrc1[s1 * 8 + head] + ad);
        float p2 = lrelu_exp(g_asrc1[s2 * 8 + head] + ad);
        float p3 = lrelu_exp(g_asrc1[s3 * 8 + head] + ad);
        float4 v0 = *(const float4*)&g_h1[(size_t)s0 * 128 + lane * 4];
        float4 v1 = *(const float4*)&g_h1[(size_t)s1 * 128 + lane * 4];
        float4 v2 = *(const float4*)&g_h1[(size_t)s2 * 128 + lane * 4];
        float4 v3 = *(const float4*)&g_h1[(size_t)s3 * 128 + lane * 4];
        acc.x += p0 * v0.x + p1 * v1.x + p2 * v2.x + p3 * v3.x;
        acc.y += p0 * v0.y + p1 * v1.y + p2 * v2.y + p3 * v3.y;
        acc.z += p0 * v0.z + p1 * v1.z + p2 * v2.z + p3 * v3.z;
        acc.w += p0 * v0.w + p1 * v1.w + p2 * v2.w + p3 * v3.w;
        denom += p0 + p1 + p2 + p3;
    }
    for (; j < end; j++) {
        int s = g_csr[j];
        float p = lrelu_exp(g_asrc1[s * 8 + head] + ad);
        float4 v = *(const float4*)&g_h1[(size_t)s * 128 + lane * 4];
        acc.x += p * v.x; acc.y += p * v.y; acc.z += p * v.z; acc.w += p * v.w;
        denom += p;
    }
    float inv = __fdividef(1.0f, denom + 1e-16f);
    float4 rv = *(const float4*)&g_res[(size_t)i * 128 + lane * 4];
    float4 bv = *(const float4*)&bias1[lane * 4];
    float4 v;
    v.x = acc.x * inv + bv.x + rv.x;
    v.y = acc.y * inv + bv.y + rv.y;
    v.z = acc.z * inv + bv.z + rv.z;
    v.w = acc.w * inv + bv.w + rv.w;
    float mu = warp_sum(v.x + v.y + v.z + v.w) * (1.0f / 128.0f);
    float dx = v.x - mu, dy = v.y - mu, dz = v.z - mu, dw = v.w - mu;
    float var = warp_sum(dx * dx + dy * dy + dz * dz + dw * dw) * (1.0f / 128.0f);
    float rs = rsqrtf(var + 1e-5f);
    float4 g4 = *(const float4*)&gamma[lane * 4];
    float4 b4 = *(const float4*)&beta[lane * 4];
    float4 o;
    o.x = dx * rs * g4.x + b4.x;
    o.y = dy * rs * g4.y + b4.y;
    o.z = dz * rs * g4.z + b4.z;
    o.w = dw * rs * g4.w + b4.w;
    o.x = o.x > 0.f ? o.x : expm1f(o.x);
    o.y = o.y > 0.f ? o.y : expm1f(o.y);
    o.z = o.z > 0.f ? o.z : expm1f(o.z);
    o.w = o.w > 0.f ? o.w : expm1f(o.w);
    *(float4*)(out + (size_t)i * 128 + lane * 4) = o;
}

// ---------------- layer2 pull aggregation + finalize (warp per node) ---------------
__global__ void __launch_bounds__(256) agg_fin2(const float* __restrict__ bias2,
                                                float* __restrict__ out, int n) {
    int i = (blockIdx.x * blockDim.x + threadIdx.x) >> 5;
    int lane = threadIdx.x & 31;
    if (i >= n) return;
    float ad = g_adst2[i];

    float2 acc;
    float denom;
    {
        float p = lrelu_exp(g_asrc2[i] + ad);
        float2 v = *(const float2*)&g_h2[(size_t)i * 64 + lane * 2];
        acc = make_float2(p * v.x, p * v.y);
        denom = p;
    }
    int start = g_rowptr[i], end = g_rowptr[i + 1];

    int j = start;
    for (; j + 4 <= end; j += 4) {
        int s0 = g_csr[j], s1 = g_csr[j + 1], s2 = g_csr[j + 2], s3 = g_csr[j + 3];
        float p0 = lrelu_exp(g_asrc2[s0] + ad);
        float p1 = lrelu_exp(g_asrc2[s1] + ad);
        float p2 = lrelu_exp(g_asrc2[s2] + ad);
        float p3 = lrelu_exp(g_asrc2[s3] + ad);
        float2 v0 = *(const float2*)&g_h2[(size_t)s0 * 64 + lane * 2];
        float2 v1 = *(const float2*)&g_h2[(size_t)s1 * 64 + lane * 2];
        float2 v2 = *(const float2*)&g_h2[(size_t)s2 * 64 + lane * 2];
        float2 v3 = *(const float2*)&g_h2[(size_t)s3 * 64 + lane * 2];
        acc.x += p0 * v0.x + p1 * v1.x + p2 * v2.x + p3 * v3.x;
        acc.y += p0 * v0.y + p1 * v1.y + p2 * v2.y + p3 * v3.y;
        denom += p0 + p1 + p2 + p3;
    }
    for (; j < end; j++) {
        int s = g_csr[j];
        float p = lrelu_exp(g_asrc2[s] + ad);
        float2 v = *(const float2*)&g_h2[(size_t)s * 64 + lane * 2];
        acc.x += p * v.x; acc.y += p * v.y;
        denom += p;
    }
    float inv = __fdividef(1.0f, denom + 1e-16f);
    float2 bv = *(const float2*)&bias2[lane * 2];
    float2 o;
    o.x = acc.x * inv + bv.x;
    o.y = acc.y * inv + bv.y;
    *(float2*)(out + (size_t)n * 128 + (size_t)i * 64 + lane * 2) = o;
}

// ---------------- launch -----------------------------------------------------------
extern "C" void kernel_launch(void* const* d_in, const int* in_sizes, int n_in,
                              void* d_out, int out_size) {
    const float* x        = (const float*)d_in[0];
    const int*   ei       = (const int*)d_in[1];
    const float* W1       = (const float*)d_in[2];
    const float* att_src1 = (const float*)d_in[3];
    const float* att_dst1 = (const float*)d_in[4];
    const float* bias1    = (const float*)d_in[5];
    const float* res_W    = (const float*)d_in[6];
    const float* gamma    = (const float*)d_in[7];
    const float* beta     = (const float*)d_in[8];
    const float* W2       = (const float*)d_in[9];
    const float* att_src2 = (const float*)d_in[10];
    const float* att_dst2 = (const float*)d_in[11];
    const float* bias2    = (const float*)d_in[12];
    float* out = (float*)d_out;

    int n = in_sizes[0] / 128;
    int E = in_sizes[1] / 2;
    if (n > NN) n = NN;
    if (E > EE) E = EE;
    const int* srcp = ei;
    const int* dstp = ei + E;

    float *p_h1, *p_res, *p_h2;
    __nv_bfloat16 *b1h, *b1l, *b2h, *b2l;
    cudaGetSymbolAddress((void**)&p_h1, g_h1);
    cudaGetSymbolAddress((void**)&p_res, g_res);
    cudaGetSymbolAddress((void**)&p_h2, g_h2);
    cudaGetSymbolAddress((void**)&b1h, g_b1hi);
    cudaGetSymbolAddress((void**)&b1l, g_b1lo);
    cudaGetSymbolAddress((void**)&b2h, g_b2hi);
    cudaGetSymbolAddress((void**)&b2l, g_b2lo);

    cudaFuncSetAttribute(mma_gemm, cudaFuncAttributeMaxDynamicSharedMemorySize, SMEM_MMA);

    // ---- CSR build ----
    int nb = (n + 1023) / 1024;
    zero_cnt<<<(n + 255) / 256, 256>>>(n);
    count_k<<<(E + 255) / 256, 256>>>(dstp, E);
    scan_blk<<<nb, 1024>>>(n);
    scan_top<<<1, 128>>>(nb);
    scan_add<<<(n + 255) / 256, 256>>>(n, E);
    scatter_k<<<(E + 255) / 256, 256>>>(srcp, dstp, E);

    // ---- layer 1: HMMA GEMM + fused att dots ----
    build_b1<<<256, 128>>>(W1, res_W);
    int mblocks = (n + 127) / 128;
    mma_gemm<<<dim3(mblocks, 4), 256, SMEM_MMA>>>(x, b1h, b1l, p_h1, p_res,
                                                  att_src1, att_dst1, n, 128, 1);
    int nwarp_blocks = (n + 7) / 8;
    agg_fin1<<<nwarp_blocks, 256>>>(bias1, gamma, beta, out, n);

    // ---- layer 2: HMMA GEMM + fused att dots ----
    build_b2<<<64, 128>>>(W2);
    mma_gemm<<<dim3(mblocks, 1), 256, SMEM_MMA>>>(out, b2h, b2l, p_h2, nullptr,
                                                  att_src2, att_dst2, n, 64, 2);
    agg_fin2<<<nwarp_blocks, 256>>>(bias2, out, n);
}